// round 4
// baseline (speedup 1.0000x reference)
#include <cuda_runtime.h>
#include <cuda_bf16.h>
#include <math.h>
#include <stdint.h>

// Problem constants
#define NN 4096
#define DD 1024
#define HH 2048

typedef __nv_bfloat16 bf16;

// ---------------- scratch (device globals; no allocations allowed) ----------
__device__ float g_colsum[DD];
__device__ float g_scores[(size_t)NN * NN];            // 64 MB

__device__ bf16 g_Xhi[(size_t)NN * DD],      g_Xlo[(size_t)NN * DD];
__device__ bf16 g_WvThi[(size_t)DD * DD],    g_WvTlo[(size_t)DD * DD];
__device__ bf16 g_feathi[(size_t)NN * 2*DD], g_featlo[(size_t)NN * 2*DD];
__device__ bf16 g_W1Thi[(size_t)HH * 2*DD],  g_W1Tlo[(size_t)HH * 2*DD];
__device__ bf16 g_hidhi[(size_t)NN * HH],    g_hidlo[(size_t)NN * HH];
__device__ bf16 g_W2Thi[(size_t)NN * HH],    g_W2Tlo[(size_t)NN * HH];
__device__ bf16 g_atthi[(size_t)NN * NN],    g_attlo[(size_t)NN * NN];
__device__ bf16 g_VThi[(size_t)DD * NN],     g_VTlo[(size_t)DD * NN];

// ---------------- helpers -----------------------------------------------------
__device__ __forceinline__ uint32_t smem_u32(const void* p) {
    uint32_t a;
    asm("{ .reg .u64 t; cvta.to.shared.u64 t, %1; cvt.u32.u64 %0, t; }" : "=r"(a) : "l"(p));
    return a;
}
__device__ __forceinline__ void cp_async16(uint32_t saddr, const void* gaddr) {
    asm volatile("cp.async.cg.shared.global [%0], [%1], 16;" :: "r"(saddr), "l"(gaddr));
}
__device__ __forceinline__ void cp_commit() {
    asm volatile("cp.async.commit_group;");
}
template<int N>
__device__ __forceinline__ void cp_wait() {
    asm volatile("cp.async.wait_group %0;" :: "n"(N));
}
__device__ __forceinline__ void ldsm_x4(uint32_t addr, uint32_t& r0, uint32_t& r1,
                                        uint32_t& r2, uint32_t& r3) {
    asm volatile("ldmatrix.sync.aligned.m8n8.x4.shared.b16 {%0,%1,%2,%3}, [%4];"
                 : "=r"(r0), "=r"(r1), "=r"(r2), "=r"(r3) : "r"(addr));
}
__device__ __forceinline__ void mma_bf16(float* c, const uint32_t* a, const uint32_t* b) {
    asm volatile(
        "mma.sync.aligned.m16n8k16.row.col.f32.bf16.bf16.f32 "
        "{%0,%1,%2,%3}, {%4,%5,%6,%7}, {%8,%9}, {%0,%1,%2,%3};"
        : "+f"(c[0]), "+f"(c[1]), "+f"(c[2]), "+f"(c[3])
        : "r"(a[0]), "r"(a[1]), "r"(a[2]), "r"(a[3]), "r"(b[0]), "r"(b[1]));
}

// ---------------- GEMM: C(M,N) = A @ B'^T via bf16x3 mma.sync -----------------
// A: [M][K] row-major bf16 (hi/lo). B': [N][K] row-major bf16 (hi/lo).
// 3 internal passes: Ahi*Bhi + Ahi*Blo + Alo*Bhi.
// CTA tile 128x256, 8 warps in 2x4 layout, each 64x64.
#define BM 128
#define BN 256
#define BK 32
#define STAGES 4
#define ROWB 80                      // padded row stride in bytes (32 bf16 + 8 pad)
#define ATILE (BM * ROWB)            // 10240 B
#define BTILE (BN * ROWB)            // 20480 B
#define STAGE_BYTES (ATILE + BTILE)  // 30720 B
#define GSMEM (STAGES * STAGE_BYTES) // 122880 B

__device__ __forceinline__ void load_chunk(uint32_t sstage,
                                           const bf16* __restrict__ Ap,
                                           const bf16* __restrict__ Bp,
                                           int K, int kt, int cy, int cx, int tid) {
    #pragma unroll
    for (int i = 0; i < 2; i++) {
        int u = tid + i * 256;               // 0..511
        int r = u >> 2, q = u & 3;
        cp_async16(sstage + r * ROWB + q * 16,
                   Ap + (size_t)(cy + r) * K + kt + q * 8);
    }
    #pragma unroll
    for (int i = 0; i < 4; i++) {
        int u = tid + i * 256;               // 0..1023
        int r = u >> 2, q = u & 3;
        cp_async16(sstage + ATILE + r * ROWB + q * 16,
                   Bp + (size_t)(cx + r) * K + kt + q * 8);
    }
}

// BIAS: 0=none, 1=per-column, 2=per-row
template<int BIAS, bool RELU, bool SPLIT>
__global__ __launch_bounds__(256, 1)
void gemm_mma(const bf16* __restrict__ Ahi, const bf16* __restrict__ Alo,
              const bf16* __restrict__ Bhi, const bf16* __restrict__ Blo,
              const float* __restrict__ bias,
              float* __restrict__ Cf, bf16* __restrict__ Chi, bf16* __restrict__ Clo,
              int M, int Nn, int K) {
    extern __shared__ char smem[];
    const uint32_t sb = smem_u32(smem);
    const int tid  = threadIdx.x;
    const int lane = tid & 31;
    const int wid  = tid >> 5;
    const int wm   = wid >> 2;          // 0..1  (M, 64 rows each)
    const int wn   = wid & 3;           // 0..3  (N, 64 cols each)
    const int cx   = blockIdx.x * BN;
    const int cy   = blockIdx.y * BM;

    const int NCK = K >> 5;
    const int NC3 = NCK * 3;

    float acc[4][8][4];
    #pragma unroll
    for (int i = 0; i < 4; i++)
        #pragma unroll
        for (int j = 0; j < 8; j++)
            #pragma unroll
            for (int k = 0; k < 4; k++) acc[i][j][k] = 0.0f;

    // per-lane ldmatrix address components
    const uint32_t aoff = (uint32_t)((wm * 64 + (lane & 15)) * ROWB + ((lane & 16) ? 16 : 0));
    const uint32_t boff = (uint32_t)((wn * 64 + (lane & 7) + ((lane & 16) ? 8 : 0)) * ROWB
                                     + ((lane & 8) ? 16 : 0));

    // prefetch
    #pragma unroll
    for (int c = 0; c < STAGES - 1; c++) {
        int pass = c / NCK;
        const bf16* Ap = (pass == 2) ? Alo : Ahi;
        const bf16* Bp = (pass == 1) ? Blo : Bhi;
        load_chunk(sb + (c % STAGES) * STAGE_BYTES, Ap, Bp, K, (c % NCK) * BK, cy, cx, tid);
        cp_commit();
    }
    cp_wait<STAGES - 2>();
    __syncthreads();

    for (int c = 0; c < NC3; c++) {
        const uint32_t st = sb + (c % STAGES) * STAGE_BYTES;
        #pragma unroll
        for (int ks = 0; ks < 2; ks++) {
            uint32_t a[4][4], b[8][2];
            #pragma unroll
            for (int mf = 0; mf < 4; mf++)
                ldsm_x4(st + aoff + mf * (16 * ROWB) + ks * 32,
                        a[mf][0], a[mf][1], a[mf][2], a[mf][3]);
            #pragma unroll
            for (int nf2 = 0; nf2 < 4; nf2++) {
                uint32_t r0, r1, r2, r3;
                ldsm_x4(st + ATILE + boff + nf2 * (16 * ROWB) + ks * 32, r0, r1, r2, r3);
                b[nf2 * 2 + 0][0] = r0; b[nf2 * 2 + 0][1] = r1;
                b[nf2 * 2 + 1][0] = r2; b[nf2 * 2 + 1][1] = r3;
            }
            #pragma unroll
            for (int mf = 0; mf < 4; mf++)
                #pragma unroll
                for (int nf = 0; nf < 8; nf++)
                    mma_bf16(acc[mf][nf], a[mf], b[nf]);
        }
        int nc = c + STAGES - 1;
        if (nc < NC3) {
            int pass = nc / NCK;
            const bf16* Ap = (pass == 2) ? Alo : Ahi;
            const bf16* Bp = (pass == 1) ? Blo : Bhi;
            load_chunk(sb + (nc % STAGES) * STAGE_BYTES, Ap, Bp, K, (nc % NCK) * BK, cy, cx, tid);
        }
        cp_commit();
        cp_wait<STAGES - 2>();
        __syncthreads();
    }

    // ---------------- epilogue -----------------------------------------------
    const int gid = lane >> 2;
    const int tig = lane & 3;
    #pragma unroll
    for (int mf = 0; mf < 4; mf++) {
        const int row0 = cy + wm * 64 + mf * 16 + gid;
        float rb0 = 0.f, rb1 = 0.f;
        if (BIAS == 2) { rb0 = bias[row0]; rb1 = bias[row0 + 8]; }
        #pragma unroll
        for (int nf = 0; nf < 8; nf++) {
            const int col = cx + wn * 64 + nf * 8 + tig * 2;
            float v0 = acc[mf][nf][0], v1 = acc[mf][nf][1];
            float v2 = acc[mf][nf][2], v3 = acc[mf][nf][3];
            if (BIAS == 1) {
                float b0 = bias[col], b1 = bias[col + 1];
                v0 += b0; v1 += b1; v2 += b0; v3 += b1;
            } else if (BIAS == 2) {
                v0 += rb0; v1 += rb0; v2 += rb1; v3 += rb1;
            }
            if (RELU) {
                v0 = fmaxf(v0, 0.f); v1 = fmaxf(v1, 0.f);
                v2 = fmaxf(v2, 0.f); v3 = fmaxf(v3, 0.f);
            }
            if (!SPLIT) {
                *(float2*)(Cf + (size_t)row0 * Nn + col)       = make_float2(v0, v1);
                *(float2*)(Cf + (size_t)(row0 + 8) * Nn + col) = make_float2(v2, v3);
            } else {
                bf16 h0 = __float2bfloat16(v0), h1 = __float2bfloat16(v1);
                bf16 h2 = __float2bfloat16(v2), h3 = __float2bfloat16(v3);
                bf16 l0 = __float2bfloat16(v0 - __bfloat162float(h0));
                bf16 l1 = __float2bfloat16(v1 - __bfloat162float(h1));
                bf16 l2 = __float2bfloat16(v2 - __bfloat162float(h2));
                bf16 l3 = __float2bfloat16(v3 - __bfloat162float(h3));
                __nv_bfloat162 hp0; hp0.x = h0; hp0.y = h1;
                __nv_bfloat162 hp1; hp1.x = h2; hp1.y = h3;
                __nv_bfloat162 lp0; lp0.x = l0; lp0.y = l1;
                __nv_bfloat162 lp1; lp1.x = l2; lp1.y = l3;
                *(__nv_bfloat162*)(Chi + (size_t)row0 * Nn + col)       = hp0;
                *(__nv_bfloat162*)(Chi + (size_t)(row0 + 8) * Nn + col) = hp1;
                *(__nv_bfloat162*)(Clo + (size_t)row0 * Nn + col)       = lp0;
                *(__nv_bfloat162*)(Clo + (size_t)(row0 + 8) * Nn + col) = lp1;
            }
        }
    }
}

// ---------------- positional encoding ----------------------------------------
__device__ __forceinline__ float pe_val(int pos, int j) {
    float even  = (float)(j & ~1);
    float denom = powf(10000.0f, even * (1.0f / (float)DD));
    float arg   = (float)pos / denom;
    return (j & 1) ? cosf(arg) : sinf(arg);
}

// ---------------- elementwise kernels -----------------------------------------
__global__ void zero_kernel(float* p, int n) {
    int i = blockIdx.x * blockDim.x + threadIdx.x;
    if (i < n) p[i] = 0.0f;
}

#define CS_ROWS 128
__global__ void colsum_kernel(const float* __restrict__ X, float* __restrict__ colsum) {
    int j  = blockIdx.x * blockDim.x + threadIdx.x;
    int r0 = blockIdx.y * CS_ROWS;
    float s = 0.0f;
    #pragma unroll 4
    for (int i = 0; i < CS_ROWS; i++) {
        int pos = r0 + i;
        s += pe_val(pos, j) * X[(size_t)pos * DD + j];
    }
    atomicAdd(&colsum[j], s);
}

__device__ __forceinline__ void split_store(bf16* hi, bf16* lo, size_t idx, float v) {
    bf16 h = __float2bfloat16(v);
    hi[idx] = h;
    lo[idx] = __float2bfloat16(v - __bfloat162float(h));
}

__global__ void feat_split_kernel(const float* __restrict__ X,
                                  const float* __restrict__ colsum,
                                  bf16* __restrict__ fhi, bf16* __restrict__ flo) {
    int idx = blockIdx.x * blockDim.x + threadIdx.x;
    int row = idx >> 11;
    int col = idx & 2047;
    float v;
    if (col < DD) {
        v = X[(size_t)row * DD + col];
    } else {
        int j = col - DD;
        float e = pe_val(row, j) * X[(size_t)row * DD + j];
        v = (colsum[j] - e) * (1.0f / (float)(NN - 1));
    }
    split_store(fhi, flo, idx, v);
}

__global__ void split_kernel(const float* __restrict__ src,
                             bf16* __restrict__ hi, bf16* __restrict__ lo, int n) {
    int i = blockIdx.x * blockDim.x + threadIdx.x;
    if (i < n) split_store(hi, lo, i, src[i]);
}

// transpose + split: src [R][C] fp32 -> dst [C][R] bf16 hi/lo
__global__ void tsplit_kernel(const float* __restrict__ src,
                              bf16* __restrict__ dhi, bf16* __restrict__ dlo,
                              int R, int C) {
    __shared__ float t[32][33];
    int bx = blockIdx.x * 32;
    int by = blockIdx.y * 32;
    int tx = threadIdx.x, ty = threadIdx.y;
    #pragma unroll
    for (int i = 0; i < 4; i++)
        t[ty + i * 8][tx] = src[(size_t)(by + ty + i * 8) * C + bx + tx];
    __syncthreads();
    #pragma unroll
    for (int i = 0; i < 4; i++) {
        float v = t[tx][ty + i * 8];
        split_store(dhi, dlo, (size_t)(bx + ty + i * 8) * R + by + tx, v);
    }
}

// row softmax over scores; writes att split bf16
__global__ void softmax_split_kernel(float* __restrict__ S,
                                     bf16* __restrict__ ahi, bf16* __restrict__ alo, int n) {
    __shared__ float red[8];
    float* row = S + (size_t)blockIdx.x * n;
    int tid = threadIdx.x;
    int lane = tid & 31, warp = tid >> 5;

    float m = -1e30f;
    for (int j = tid; j < n; j += 256) m = fmaxf(m, row[j]);
    #pragma unroll
    for (int o = 16; o > 0; o >>= 1) m = fmaxf(m, __shfl_xor_sync(0xffffffffu, m, o));
    if (lane == 0) red[warp] = m;
    __syncthreads();
    if (tid < 8) {
        float v = red[tid];
        #pragma unroll
        for (int o = 4; o > 0; o >>= 1) v = fmaxf(v, __shfl_xor_sync(0xffu, v, o));
        if (tid == 0) red[0] = v;
    }
    __syncthreads();
    m = red[0];
    __syncthreads();

    float s = 0.0f;
    for (int j = tid; j < n; j += 256) {
        float e = __expf(row[j] - m);
        row[j] = e;
        s += e;
    }
    #pragma unroll
    for (int o = 16; o > 0; o >>= 1) s += __shfl_xor_sync(0xffffffffu, s, o);
    if (lane == 0) red[warp] = s;
    __syncthreads();
    if (tid < 8) {
        float v = red[tid];
        #pragma unroll
        for (int o = 4; o > 0; o >>= 1) v += __shfl_xor_sync(0xffu, v, o);
        if (tid == 0) red[0] = v;
    }
    __syncthreads();
    float inv = 1.0f / red[0];
    size_t base = (size_t)blockIdx.x * n;
    for (int j = tid; j < n; j += 256) {
        float a = row[j] * inv;
        split_store(ahi, alo, base + j, a);
    }
}

// ---------------- driver ------------------------------------------------------
extern "C" void kernel_launch(void* const* d_in, const int* in_sizes, int n_in,
                              void* d_out, int out_size) {
    const float* X  = (const float*)d_in[0];
    const float* Wv = (const float*)d_in[2];
    const float* bv = (const float*)d_in[3];
    const float* W1 = (const float*)d_in[4];
    const float* b1 = (const float*)d_in[5];
    const float* W2 = (const float*)d_in[6];
    const float* b2 = (const float*)d_in[7];
    float* out = (float*)d_out;

    void* p;
    cudaGetSymbolAddress(&p, g_colsum); float* colsum = (float*)p;
    cudaGetSymbolAddress(&p, g_scores); float* scores = (float*)p;
    cudaGetSymbolAddress(&p, g_Xhi);    bf16* Xhi   = (bf16*)p;
    cudaGetSymbolAddress(&p, g_Xlo);    bf16* Xlo   = (bf16*)p;
    cudaGetSymbolAddress(&p, g_WvThi);  bf16* WvThi = (bf16*)p;
    cudaGetSymbolAddress(&p, g_WvTlo);  bf16* WvTlo = (bf16*)p;
    cudaGetSymbolAddress(&p, g_feathi); bf16* fthi  = (bf16*)p;
    cudaGetSymbolAddress(&p, g_featlo); bf16* ftlo  = (bf16*)p;
    cudaGetSymbolAddress(&p, g_W1Thi);  bf16* W1Thi = (bf16*)p;
    cudaGetSymbolAddress(&p, g_W1Tlo);  bf16* W1Tlo = (bf16*)p;
    cudaGetSymbolAddress(&p, g_hidhi);  bf16* hdhi  = (bf16*)p;
    cudaGetSymbolAddress(&p, g_hidlo);  bf16* hdlo  = (bf16*)p;
    cudaGetSymbolAddress(&p, g_W2Thi);  bf16* W2Thi = (bf16*)p;
    cudaGetSymbolAddress(&p, g_W2Tlo);  bf16* W2Tlo = (bf16*)p;
    cudaGetSymbolAddress(&p, g_atthi);  bf16* athi  = (bf16*)p;
    cudaGetSymbolAddress(&p, g_attlo);  bf16* atlo  = (bf16*)p;
    cudaGetSymbolAddress(&p, g_VThi);   bf16* VThi  = (bf16*)p;
    cudaGetSymbolAddress(&p, g_VTlo);   bf16* VTlo  = (bf16*)p;

    cudaFuncSetAttribute(gemm_mma<1, false, false>,
                         cudaFuncAttributeMaxDynamicSharedMemorySize, GSMEM);
    cudaFuncSetAttribute(gemm_mma<1, true,  true>,
                         cudaFuncAttributeMaxDynamicSharedMemorySize, GSMEM);
    cudaFuncSetAttribute(gemm_mma<0, false, false>,
                         cudaFuncAttributeMaxDynamicSharedMemorySize, GSMEM);
    cudaFuncSetAttribute(gemm_mma<2, false, true>,
                         cudaFuncAttributeMaxDynamicSharedMemorySize, GSMEM);

    // --- operand prep --------------------------------------------------------
    zero_kernel<<<4, 256>>>(colsum, DD);
    colsum_kernel<<<dim3(DD / 256, NN / CS_ROWS), 256>>>(X, colsum);
    feat_split_kernel<<<(NN * 2 * DD) / 256, 256>>>(X, colsum, fthi, ftlo);
    split_kernel<<<(NN * DD) / 256, 256>>>(X, Xhi, Xlo, NN * DD);
    tsplit_kernel<<<dim3(DD / 32, DD / 32),     dim3(32, 8)>>>(Wv, WvThi, WvTlo, DD, DD);
    tsplit_kernel<<<dim3(HH / 32, (2*DD) / 32), dim3(32, 8)>>>(W1, W1Thi, W1Tlo, 2 * DD, HH);
    tsplit_kernel<<<dim3(NN / 32, HH / 32),     dim3(32, 8)>>>(W2, W2Thi, W2Tlo, HH, NN);

    // --- GEMM1 (transposed): VT = WvT @ X^T + bv(row)  (M=1024, N=4096, K=1024)
    // C[m][n] = sum_k Wv[k][m] X[n][k] + bv[m] = V[n][m]; split output -> VT hi/lo
    gemm_mma<2, false, true><<<dim3(NN / BN, DD / BM), 256, GSMEM>>>(
        WvThi, WvTlo, Xhi, Xlo, bv, nullptr, VThi, VTlo, DD, NN, DD);

    // --- GEMM2: hidden = relu(feat @ W1 + b1) (4096,2048,2048), split out ----
    gemm_mma<1, true, true><<<dim3(HH / BN, NN / BM), 256, GSMEM>>>(
        fthi, ftlo, W1Thi, W1Tlo, b1, nullptr, hdhi, hdlo, NN, HH, 2 * DD);

    // --- GEMM3: scores = hidden @ W2 + b2 (4096,4096,2048) -------------------
    gemm_mma<1, false, false><<<dim3(NN / BN, NN / BM), 256, GSMEM>>>(
        hdhi, hdlo, W2Thi, W2Tlo, b2, scores, nullptr, nullptr, NN, NN, HH);

    // --- softmax -> att split -------------------------------------------------
    softmax_split_kernel<<<NN, 256>>>(scores, athi, atlo, NN);

    // --- GEMM4: out = att @ V (4096,1024,4096) --------------------------------
    gemm_mma<0, false, false><<<dim3(DD / BN, NN / BM), 256, GSMEM>>>(
        athi, atlo, VThi, VTlo, nullptr, out, nullptr, nullptr, NN, DD, NN);
}

// round 5
// speedup vs baseline: 1.1712x; 1.1712x over previous
#include <cuda_runtime.h>
#include <cuda_bf16.h>
#include <math.h>
#include <stdint.h>

// Problem constants
#define NN 4096
#define DD 1024
#define HH 2048

typedef __nv_bfloat16 bf16;

// ---------------- scratch (device globals; no allocations allowed) ----------
__device__ float g_colsum[DD];
__device__ float g_scores[(size_t)NN * NN];            // 64 MB

__device__ bf16 g_Xhi[(size_t)NN * DD],     g_Xlo[(size_t)NN * DD];
__device__ bf16 g_loohi[(size_t)NN * DD],   g_loolo[(size_t)NN * DD];
__device__ bf16 g_WvThi[(size_t)DD * DD],   g_WvTlo[(size_t)DD * DD];
__device__ bf16 g_W1Thi[(size_t)HH * 2*DD], g_W1Tlo[(size_t)HH * 2*DD];
__device__ bf16 g_hidhi[(size_t)NN * HH],   g_hidlo[(size_t)NN * HH];
__device__ bf16 g_W2Thi[(size_t)NN * HH],   g_W2Tlo[(size_t)NN * HH];
__device__ bf16 g_atthi[(size_t)NN * NN],   g_attlo[(size_t)NN * NN];
__device__ bf16 g_VThi[(size_t)DD * NN],    g_VTlo[(size_t)DD * NN];

// ---------------- helpers -----------------------------------------------------
__device__ __forceinline__ uint32_t smem_u32(const void* p) {
    uint32_t a;
    asm("{ .reg .u64 t; cvta.to.shared.u64 t, %1; cvt.u32.u64 %0, t; }" : "=r"(a) : "l"(p));
    return a;
}
__device__ __forceinline__ void cp_async16(uint32_t saddr, const void* gaddr) {
    asm volatile("cp.async.cg.shared.global [%0], [%1], 16;" :: "r"(saddr), "l"(gaddr));
}
__device__ __forceinline__ void cp_commit() {
    asm volatile("cp.async.commit_group;");
}
template<int N>
__device__ __forceinline__ void cp_wait() {
    asm volatile("cp.async.wait_group %0;" :: "n"(N));
}
__device__ __forceinline__ void ldsm_x4(uint32_t addr, uint32_t& r0, uint32_t& r1,
                                        uint32_t& r2, uint32_t& r3) {
    asm volatile("ldmatrix.sync.aligned.m8n8.x4.shared.b16 {%0,%1,%2,%3}, [%4];"
                 : "=r"(r0), "=r"(r1), "=r"(r2), "=r"(r3) : "r"(addr));
}
__device__ __forceinline__ void mma_bf16(float* c, const uint32_t* a, const uint32_t* b) {
    asm volatile(
        "mma.sync.aligned.m16n8k16.row.col.f32.bf16.bf16.f32 "
        "{%0,%1,%2,%3}, {%4,%5,%6,%7}, {%8,%9}, {%0,%1,%2,%3};"
        : "+f"(c[0]), "+f"(c[1]), "+f"(c[2]), "+f"(c[3])
        : "r"(a[0]), "r"(a[1]), "r"(a[2]), "r"(a[3]), "r"(b[0]), "r"(b[1]));
}

// ---------------- GEMM: C(M,N) = [A|A2] @ B'^T via bf16x3 mma.sync ------------
// A: [M][K1] + A2: [M][K-K1] row-major bf16 (hi/lo). B': [N][K] row-major.
// 3 internal passes: Ahi*Bhi + Ahi*Blo + Alo*Bhi.
#define BM 128
#define BN 128
#define BK 32
#define STAGES 3
#define ROWB 80                      // padded row stride in bytes (32 bf16 + 8 pad)
#define ATILE (BM * ROWB)            // 10240 B
#define STAGE_BYTES (2 * ATILE)      // 20480 B
#define GSMEM (STAGES * STAGE_BYTES) // 61440 B

__device__ __forceinline__ void load_chunk(uint32_t sstage,
                                           const bf16* __restrict__ Ap, int sA, int ka,
                                           const bf16* __restrict__ Bp, int sB, int kb,
                                           int cy, int cx, int tid) {
    #pragma unroll
    for (int i = 0; i < 2; i++) {
        int u = tid + i * 256;
        int r = u >> 2, q = u & 3;
        cp_async16(sstage + r * ROWB + q * 16, Ap + (size_t)(cy + r) * sA + ka + q * 8);
    }
    #pragma unroll
    for (int i = 0; i < 2; i++) {
        int u = tid + i * 256;
        int r = u >> 2, q = u & 3;
        cp_async16(sstage + ATILE + r * ROWB + q * 16, Bp + (size_t)(cx + r) * sB + kb + q * 8);
    }
}

// BIAS: 0=none, 1=per-column, 2=per-row
template<int BIAS, bool RELU, bool SPLIT>
__global__ __launch_bounds__(256, 2)
void gemm_mma(const bf16* __restrict__ Ahi,  const bf16* __restrict__ Alo,
              const bf16* __restrict__ A2hi, const bf16* __restrict__ A2lo,
              const bf16* __restrict__ Bhi,  const bf16* __restrict__ Blo,
              const float* __restrict__ bias,
              float* __restrict__ Cf, bf16* __restrict__ Chi, bf16* __restrict__ Clo,
              int Nn, int K, int K1) {
    extern __shared__ char smem[];
    const uint32_t sb = smem_u32(smem);
    const int tid  = threadIdx.x;
    const int lane = tid & 31;
    const int wid  = tid >> 5;
    const int wm   = wid >> 2;          // 0..1  (M)
    const int wn   = wid & 3;           // 0..3  (N)
    const int cx   = blockIdx.x * BN;
    const int cy   = blockIdx.y * BM;
    const int K2   = K - K1;

    const int NCK = K >> 5;
    const int NC3 = NCK * 3;

    float acc[4][4][4];
    #pragma unroll
    for (int i = 0; i < 4; i++)
        #pragma unroll
        for (int j = 0; j < 4; j++)
            #pragma unroll
            for (int k = 0; k < 4; k++) acc[i][j][k] = 0.0f;

    const uint32_t aoff = (uint32_t)((wm * 64 + (lane & 15)) * ROWB + ((lane & 16) ? 16 : 0));
    const uint32_t boff = (uint32_t)((wn * 32 + (lane & 7) + ((lane & 16) ? 8 : 0)) * ROWB
                                     + ((lane & 8) ? 16 : 0));

    // prefetch
    #pragma unroll
    for (int c = 0; c < STAGES - 1; c++) {
        int pass = c / NCK;
        int k = (c % NCK) * BK;
        const bf16* Bp = (pass == 1) ? Blo : Bhi;
        const bf16* Ap;
        int ka, sA;
        if (k < K1) { Ap = (pass == 2) ? Alo  : Ahi;  ka = k;      sA = K1; }
        else        { Ap = (pass == 2) ? A2lo : A2hi; ka = k - K1; sA = K2; }
        load_chunk(sb + (c % STAGES) * STAGE_BYTES, Ap, sA, ka, Bp, K, k, cy, cx, tid);
        cp_commit();
    }
    cp_wait<STAGES - 2>();
    __syncthreads();

    for (int c = 0; c < NC3; c++) {
        const uint32_t st = sb + (c % STAGES) * STAGE_BYTES;
        #pragma unroll
        for (int ks = 0; ks < 2; ks++) {
            uint32_t a[4][4], b[4][2];
            #pragma unroll
            for (int mf = 0; mf < 4; mf++)
                ldsm_x4(st + aoff + mf * (16 * ROWB) + ks * 32,
                        a[mf][0], a[mf][1], a[mf][2], a[mf][3]);
            #pragma unroll
            for (int nf2 = 0; nf2 < 2; nf2++) {
                uint32_t r0, r1, r2, r3;
                ldsm_x4(st + ATILE + boff + nf2 * (16 * ROWB) + ks * 32, r0, r1, r2, r3);
                b[nf2 * 2 + 0][0] = r0; b[nf2 * 2 + 0][1] = r1;
                b[nf2 * 2 + 1][0] = r2; b[nf2 * 2 + 1][1] = r3;
            }
            #pragma unroll
            for (int mf = 0; mf < 4; mf++)
                #pragma unroll
                for (int nf = 0; nf < 4; nf++)
                    mma_bf16(acc[mf][nf], a[mf], b[nf]);
        }
        int nc = c + STAGES - 1;
        if (nc < NC3) {
            int pass = nc / NCK;
            int k = (nc % NCK) * BK;
            const bf16* Bp = (pass == 1) ? Blo : Bhi;
            const bf16* Ap;
            int ka, sA;
            if (k < K1) { Ap = (pass == 2) ? Alo  : Ahi;  ka = k;      sA = K1; }
            else        { Ap = (pass == 2) ? A2lo : A2hi; ka = k - K1; sA = K2; }
            load_chunk(sb + (nc % STAGES) * STAGE_BYTES, Ap, sA, ka, Bp, K, k, cy, cx, tid);
        }
        cp_commit();
        cp_wait<STAGES - 2>();
        __syncthreads();
    }

    // ---------------- epilogue -----------------------------------------------
    const int gid = lane >> 2;
    const int tig = lane & 3;
    #pragma unroll
    for (int mf = 0; mf < 4; mf++) {
        const int row0 = cy + wm * 64 + mf * 16 + gid;
        float rb0 = 0.f, rb1 = 0.f;
        if (BIAS == 2) { rb0 = bias[row0]; rb1 = bias[row0 + 8]; }
        #pragma unroll
        for (int nf = 0; nf < 4; nf++) {
            const int col = cx + wn * 32 + nf * 8 + tig * 2;
            float v0 = acc[mf][nf][0], v1 = acc[mf][nf][1];
            float v2 = acc[mf][nf][2], v3 = acc[mf][nf][3];
            if (BIAS == 1) {
                float b0 = bias[col], b1 = bias[col + 1];
                v0 += b0; v1 += b1; v2 += b0; v3 += b1;
            } else if (BIAS == 2) {
                v0 += rb0; v1 += rb0; v2 += rb1; v3 += rb1;
            }
            if (RELU) {
                v0 = fmaxf(v0, 0.f); v1 = fmaxf(v1, 0.f);
                v2 = fmaxf(v2, 0.f); v3 = fmaxf(v3, 0.f);
            }
            if (!SPLIT) {
                *(float2*)(Cf + (size_t)row0 * Nn + col)       = make_float2(v0, v1);
                *(float2*)(Cf + (size_t)(row0 + 8) * Nn + col) = make_float2(v2, v3);
            } else {
                bf16 h0 = __float2bfloat16(v0), h1 = __float2bfloat16(v1);
                bf16 h2 = __float2bfloat16(v2), h3 = __float2bfloat16(v3);
                bf16 l0 = __float2bfloat16(v0 - __bfloat162float(h0));
                bf16 l1 = __float2bfloat16(v1 - __bfloat162float(h1));
                bf16 l2 = __float2bfloat16(v2 - __bfloat162float(h2));
                bf16 l3 = __float2bfloat16(v3 - __bfloat162float(h3));
                __nv_bfloat162 hp0; hp0.x = h0; hp0.y = h1;
                __nv_bfloat162 hp1; hp1.x = h2; hp1.y = h3;
                __nv_bfloat162 lp0; lp0.x = l0; lp0.y = l1;
                __nv_bfloat162 lp1; lp1.x = l2; lp1.y = l3;
                *(__nv_bfloat162*)(Chi + (size_t)row0 * Nn + col)       = hp0;
                *(__nv_bfloat162*)(Chi + (size_t)(row0 + 8) * Nn + col) = hp1;
                *(__nv_bfloat162*)(Clo + (size_t)row0 * Nn + col)       = lp0;
                *(__nv_bfloat162*)(Clo + (size_t)(row0 + 8) * Nn + col) = lp1;
            }
        }
    }
}

// ---------------- positional encoding ----------------------------------------
__device__ __forceinline__ float pe_val(int pos, int j) {
    float even  = (float)(j & ~1);
    float denom = powf(10000.0f, even * (1.0f / (float)DD));
    float arg   = (float)pos / denom;
    return (j & 1) ? cosf(arg) : sinf(arg);
}

// ---------------- elementwise kernels -----------------------------------------
__global__ void zero_kernel(float* p, int n) {
    int i = blockIdx.x * blockDim.x + threadIdx.x;
    if (i < n) p[i] = 0.0f;
}

#define CS_ROWS 128
__global__ void colsum_kernel(const float* __restrict__ X, float* __restrict__ colsum) {
    int j  = blockIdx.x * blockDim.x + threadIdx.x;
    int r0 = blockIdx.y * CS_ROWS;
    float s = 0.0f;
    #pragma unroll 4
    for (int i = 0; i < CS_ROWS; i++) {
        int pos = r0 + i;
        s += pe_val(pos, j) * X[(size_t)pos * DD + j];
    }
    atomicAdd(&colsum[j], s);
}

__device__ __forceinline__ void split_store(bf16* hi, bf16* lo, size_t idx, float v) {
    bf16 h = __float2bfloat16(v);
    hi[idx] = h;
    lo[idx] = __float2bfloat16(v - __bfloat162float(h));
}

// loo = (colsum - PE*X)/(N-1) -> split bf16, plus split of X itself
__global__ void loo_split_kernel(const float* __restrict__ X,
                                 const float* __restrict__ colsum,
                                 bf16* __restrict__ lhi, bf16* __restrict__ llo,
                                 bf16* __restrict__ xhi, bf16* __restrict__ xlo) {
    int idx = blockIdx.x * blockDim.x + threadIdx.x;   // over N*D
    int row = idx >> 10;
    int j   = idx & 1023;
    float x = X[idx];
    split_store(xhi, xlo, idx, x);
    float e = pe_val(row, j) * x;
    float v = (colsum[j] - e) * (1.0f / (float)(NN - 1));
    split_store(lhi, llo, idx, v);
}

// transpose + split: src [R][C] fp32 -> dst [C][R] bf16 hi/lo
__global__ void tsplit_kernel(const float* __restrict__ src,
                              bf16* __restrict__ dhi, bf16* __restrict__ dlo,
                              int R, int C) {
    __shared__ float t[32][33];
    int bx = blockIdx.x * 32;
    int by = blockIdx.y * 32;
    int tx = threadIdx.x, ty = threadIdx.y;
    #pragma unroll
    for (int i = 0; i < 4; i++)
        t[ty + i * 8][tx] = src[(size_t)(by + ty + i * 8) * C + bx + tx];
    __syncthreads();
    #pragma unroll
    for (int i = 0; i < 4; i++) {
        float v = t[tx][ty + i * 8];
        split_store(dhi, dlo, (size_t)(bx + ty + i * 8) * R + by + tx, v);
    }
}

// row softmax over scores; writes att split bf16
__global__ void softmax_split_kernel(float* __restrict__ S,
                                     bf16* __restrict__ ahi, bf16* __restrict__ alo, int n) {
    __shared__ float red[8];
    float* row = S + (size_t)blockIdx.x * n;
    int tid = threadIdx.x;
    int lane = tid & 31, warp = tid >> 5;

    float m = -1e30f;
    for (int j = tid; j < n; j += 256) m = fmaxf(m, row[j]);
    #pragma unroll
    for (int o = 16; o > 0; o >>= 1) m = fmaxf(m, __shfl_xor_sync(0xffffffffu, m, o));
    if (lane == 0) red[warp] = m;
    __syncthreads();
    if (tid < 8) {
        float v = red[tid];
        #pragma unroll
        for (int o = 4; o > 0; o >>= 1) v = fmaxf(v, __shfl_xor_sync(0xffu, v, o));
        if (tid == 0) red[0] = v;
    }
    __syncthreads();
    m = red[0];
    __syncthreads();

    float s = 0.0f;
    for (int j = tid; j < n; j += 256) {
        float e = __expf(row[j] - m);
        row[j] = e;
        s += e;
    }
    #pragma unroll
    for (int o = 16; o > 0; o >>= 1) s += __shfl_xor_sync(0xffffffffu, s, o);
    if (lane == 0) red[warp] = s;
    __syncthreads();
    if (tid < 8) {
        float v = red[tid];
        #pragma unroll
        for (int o = 4; o > 0; o >>= 1) v += __shfl_xor_sync(0xffu, v, o);
        if (tid == 0) red[0] = v;
    }
    __syncthreads();
    float inv = 1.0f / red[0];
    size_t base = (size_t)blockIdx.x * n;
    for (int j = tid; j < n; j += 256) {
        float a = row[j] * inv;
        split_store(ahi, alo, base + j, a);
    }
}

// ---------------- driver ------------------------------------------------------
extern "C" void kernel_launch(void* const* d_in, const int* in_sizes, int n_in,
                              void* d_out, int out_size) {
    const float* X  = (const float*)d_in[0];
    const float* Wv = (const float*)d_in[2];
    const float* bv = (const float*)d_in[3];
    const float* W1 = (const float*)d_in[4];
    const float* b1 = (const float*)d_in[5];
    const float* W2 = (const float*)d_in[6];
    const float* b2 = (const float*)d_in[7];
    float* out = (float*)d_out;

    void* p;
    cudaGetSymbolAddress(&p, g_colsum); float* colsum = (float*)p;
    cudaGetSymbolAddress(&p, g_scores); float* scores = (float*)p;
    cudaGetSymbolAddress(&p, g_Xhi);    bf16* Xhi   = (bf16*)p;
    cudaGetSymbolAddress(&p, g_Xlo);    bf16* Xlo   = (bf16*)p;
    cudaGetSymbolAddress(&p, g_loohi);  bf16* loohi = (bf16*)p;
    cudaGetSymbolAddress(&p, g_loolo);  bf16* loolo = (bf16*)p;
    cudaGetSymbolAddress(&p, g_WvThi);  bf16* WvThi = (bf16*)p;
    cudaGetSymbolAddress(&p, g_WvTlo);  bf16* WvTlo = (bf16*)p;
    cudaGetSymbolAddress(&p, g_W1Thi);  bf16* W1Thi = (bf16*)p;
    cudaGetSymbolAddress(&p, g_W1Tlo);  bf16* W1Tlo = (bf16*)p;
    cudaGetSymbolAddress(&p, g_hidhi);  bf16* hdhi  = (bf16*)p;
    cudaGetSymbolAddress(&p, g_hidlo);  bf16* hdlo  = (bf16*)p;
    cudaGetSymbolAddress(&p, g_W2Thi);  bf16* W2Thi = (bf16*)p;
    cudaGetSymbolAddress(&p, g_W2Tlo);  bf16* W2Tlo = (bf16*)p;
    cudaGetSymbolAddress(&p, g_atthi);  bf16* athi  = (bf16*)p;
    cudaGetSymbolAddress(&p, g_attlo);  bf16* atlo  = (bf16*)p;
    cudaGetSymbolAddress(&p, g_VThi);   bf16* VThi  = (bf16*)p;
    cudaGetSymbolAddress(&p, g_VTlo);   bf16* VTlo  = (bf16*)p;

    cudaFuncSetAttribute(gemm_mma<1, false, false>,
                         cudaFuncAttributeMaxDynamicSharedMemorySize, GSMEM);
    cudaFuncSetAttribute(gemm_mma<1, true,  true>,
                         cudaFuncAttributeMaxDynamicSharedMemorySize, GSMEM);
    cudaFuncSetAttribute(gemm_mma<0, false, false>,
                         cudaFuncAttributeMaxDynamicSharedMemorySize, GSMEM);
    cudaFuncSetAttribute(gemm_mma<2, false, true>,
                         cudaFuncAttributeMaxDynamicSharedMemorySize, GSMEM);

    // --- operand prep --------------------------------------------------------
    zero_kernel<<<4, 256>>>(colsum, DD);
    colsum_kernel<<<dim3(DD / 256, NN / CS_ROWS), 256>>>(X, colsum);
    loo_split_kernel<<<(NN * DD) / 256, 256>>>(X, colsum, loohi, loolo, Xhi, Xlo);
    tsplit_kernel<<<dim3(DD / 32, DD / 32),     dim3(32, 8)>>>(Wv, WvThi, WvTlo, DD, DD);
    tsplit_kernel<<<dim3(HH / 32, (2*DD) / 32), dim3(32, 8)>>>(W1, W1Thi, W1Tlo, 2 * DD, HH);
    tsplit_kernel<<<dim3(NN / 32, HH / 32),     dim3(32, 8)>>>(W2, W2Thi, W2Tlo, HH, NN);

    // --- GEMM1 (transposed): VT = WvT @ X^T + bv(row)  (M=1024, N=4096, K=1024)
    gemm_mma<2, false, true><<<dim3(NN / BN, DD / BM), 256, GSMEM>>>(
        WvThi, WvTlo, WvThi, WvTlo, Xhi, Xlo, bv,
        nullptr, VThi, VTlo, NN, DD, DD);

    // --- GEMM2: hidden = relu([X|loo] @ W1 + b1) (4096,2048,K=2048,K1=1024) --
    gemm_mma<1, true, true><<<dim3(HH / BN, NN / BM), 256, GSMEM>>>(
        Xhi, Xlo, loohi, loolo, W1Thi, W1Tlo, b1,
        nullptr, hdhi, hdlo, HH, 2 * DD, DD);

    // --- GEMM3: scores = hidden @ W2 + b2 (4096,4096,2048) -------------------
    gemm_mma<1, false, false><<<dim3(NN / BN, NN / BM), 256, GSMEM>>>(
        hdhi, hdlo, hdhi, hdlo, W2Thi, W2Tlo, b2,
        scores, nullptr, nullptr, NN, HH, HH);

    // --- softmax -> att split -------------------------------------------------
    softmax_split_kernel<<<NN, 256>>>(scores, athi, atlo, NN);

    // --- GEMM4: out = att @ V (4096,1024,4096) --------------------------------
    gemm_mma<0, false, false><<<dim3(DD / BN, NN / BM), 256, GSMEM>>>(
        athi, atlo, athi, atlo, VThi, VTlo, nullptr,
        out, nullptr, nullptr, DD, NN, NN);
}

// round 6
// speedup vs baseline: 1.2125x; 1.0353x over previous
#include <cuda_runtime.h>
#include <cuda_bf16.h>
#include <math.h>
#include <stdint.h>

// Problem constants
#define NN 4096
#define DD 1024
#define HH 2048

typedef __nv_bfloat16 bf16;

// ---------------- scratch (device globals; no allocations allowed) ----------
__device__ float g_colsum[DD];
__device__ float g_scores[(size_t)NN * NN];            // 64 MB

__device__ bf16 g_Xhi[(size_t)NN * DD],     g_Xlo[(size_t)NN * DD];
__device__ bf16 g_loohi[(size_t)NN * DD],   g_loolo[(size_t)NN * DD];
__device__ bf16 g_WvThi[(size_t)DD * DD],   g_WvTlo[(size_t)DD * DD];
__device__ bf16 g_W1Thi[(size_t)HH * 2*DD], g_W1Tlo[(size_t)HH * 2*DD];
__device__ bf16 g_hidhi[(size_t)NN * HH],   g_hidlo[(size_t)NN * HH];
__device__ bf16 g_W2Thi[(size_t)NN * HH],   g_W2Tlo[(size_t)NN * HH];
__device__ bf16 g_atthi[(size_t)NN * NN],   g_attlo[(size_t)NN * NN];
__device__ bf16 g_VThi[(size_t)DD * NN],    g_VTlo[(size_t)DD * NN];

// ---------------- helpers -----------------------------------------------------
__device__ __forceinline__ uint32_t smem_u32(const void* p) {
    uint32_t a;
    asm("{ .reg .u64 t; cvta.to.shared.u64 t, %1; cvt.u32.u64 %0, t; }" : "=r"(a) : "l"(p));
    return a;
}
__device__ __forceinline__ void cp_async16(uint32_t saddr, const void* gaddr) {
    asm volatile("cp.async.cg.shared.global [%0], [%1], 16;" :: "r"(saddr), "l"(gaddr));
}
__device__ __forceinline__ void cp_commit() {
    asm volatile("cp.async.commit_group;");
}
template<int N>
__device__ __forceinline__ void cp_wait() {
    asm volatile("cp.async.wait_group %0;" :: "n"(N));
}
__device__ __forceinline__ void ldsm_x4(uint32_t addr, uint32_t& r0, uint32_t& r1,
                                        uint32_t& r2, uint32_t& r3) {
    asm volatile("ldmatrix.sync.aligned.m8n8.x4.shared.b16 {%0,%1,%2,%3}, [%4];"
                 : "=r"(r0), "=r"(r1), "=r"(r2), "=r"(r3) : "r"(addr));
}
__device__ __forceinline__ void mma_bf16(float* c, const uint32_t* a, const uint32_t* b) {
    asm volatile(
        "mma.sync.aligned.m16n8k16.row.col.f32.bf16.bf16.f32 "
        "{%0,%1,%2,%3}, {%4,%5,%6,%7}, {%8,%9}, {%0,%1,%2,%3};"
        : "+f"(c[0]), "+f"(c[1]), "+f"(c[2]), "+f"(c[3])
        : "r"(a[0]), "r"(a[1]), "r"(a[2]), "r"(a[3]), "r"(b[0]), "r"(b[1]));
}

// ---------------- GEMM: C(M,N) = [A|A2] @ B'^T, fused bf16x3 ------------------
// Per k16: acc += Ahi*Blo + Ahi*Bhi + Alo*Bhi (single k sweep, one accumulator).
#define BM 128
#define BN 128
#define BK 32
#define ROWB 80                      // padded row stride (32 bf16 + 8B pad)
#define TILE (BM * ROWB)             // 10240 B
#define T_AHI 0
#define T_ALO TILE
#define T_BHI (2 * TILE)
#define T_BLO (3 * TILE)
#define STAGE_BYTES (4 * TILE)       // 40960 B
#define GSMEM (2 * STAGE_BYTES)      // 81920 B (2 stages)

__device__ __forceinline__ void load_chunk(uint32_t sstage,
                                           const bf16* __restrict__ Ahi,
                                           const bf16* __restrict__ Alo, int sA, int ka,
                                           const bf16* __restrict__ Bhi,
                                           const bf16* __restrict__ Blo, int sB, int kb,
                                           int cy, int cx, int tid) {
    #pragma unroll
    for (int i = 0; i < 2; i++) {
        int u = tid + i * 256;       // 0..511
        int r = u >> 2, q = u & 3;
        uint32_t so = (uint32_t)(r * ROWB + q * 16);
        size_t ga = (size_t)(cy + r) * sA + ka + q * 8;
        size_t gb = (size_t)(cx + r) * sB + kb + q * 8;
        cp_async16(sstage + T_AHI + so, Ahi + ga);
        cp_async16(sstage + T_ALO + so, Alo + ga);
        cp_async16(sstage + T_BHI + so, Bhi + gb);
        cp_async16(sstage + T_BLO + so, Blo + gb);
    }
}

// BIAS: 0=none, 1=per-column, 2=per-row
template<int BIAS, bool RELU, bool SPLIT>
__global__ __launch_bounds__(256, 2)
void gemm_mma(const bf16* __restrict__ Ahi,  const bf16* __restrict__ Alo,
              const bf16* __restrict__ A2hi, const bf16* __restrict__ A2lo,
              const bf16* __restrict__ Bhi,  const bf16* __restrict__ Blo,
              const float* __restrict__ bias,
              float* __restrict__ Cf, bf16* __restrict__ Chi, bf16* __restrict__ Clo,
              int Nn, int K, int K1) {
    extern __shared__ char smem[];
    const uint32_t sb = smem_u32(smem);
    const int tid  = threadIdx.x;
    const int lane = tid & 31;
    const int wid  = tid >> 5;
    const int wm   = wid >> 2;          // 0..1  (M)
    const int wn   = wid & 3;           // 0..3  (N)
    const int cx   = blockIdx.x * BN;
    const int cy   = blockIdx.y * BM;
    const int K2   = K - K1;
    const int NCK  = K >> 5;

    float acc[4][4][4];
    #pragma unroll
    for (int i = 0; i < 4; i++)
        #pragma unroll
        for (int j = 0; j < 4; j++)
            #pragma unroll
            for (int k = 0; k < 4; k++) acc[i][j][k] = 0.0f;

    const uint32_t aoff = (uint32_t)((wm * 64 + (lane & 15)) * ROWB + ((lane & 16) ? 16 : 0));
    const uint32_t boff = (uint32_t)((wn * 32 + (lane & 7) + ((lane & 16) ? 8 : 0)) * ROWB
                                     + ((lane & 8) ? 16 : 0));

    // prefetch chunk 0
    {
        const bf16 *Ap_hi, *Ap_lo; int ka, sA;
        if (0 < K1) { Ap_hi = Ahi;  Ap_lo = Alo;  ka = 0; sA = K1; }
        else        { Ap_hi = A2hi; Ap_lo = A2lo; ka = 0; sA = K2; }
        load_chunk(sb, Ap_hi, Ap_lo, sA, ka, Bhi, Blo, K, 0, cy, cx, tid);
        cp_commit();
    }

    for (int c = 0; c < NCK; c++) {
        cp_wait<0>();
        __syncthreads();
        // issue next chunk load before compute (S=2 overlap)
        if (c + 1 < NCK) {
            int k = (c + 1) * BK;
            const bf16 *Ap_hi, *Ap_lo; int ka, sA;
            if (k < K1) { Ap_hi = Ahi;  Ap_lo = Alo;  ka = k;      sA = K1; }
            else        { Ap_hi = A2hi; Ap_lo = A2lo; ka = k - K1; sA = K2; }
            load_chunk(sb + ((c + 1) & 1) * STAGE_BYTES, Ap_hi, Ap_lo, sA, ka,
                       Bhi, Blo, K, k, cy, cx, tid);
            cp_commit();
        }

        const uint32_t st = sb + (c & 1) * STAGE_BYTES;
        #pragma unroll
        for (int ks = 0; ks < 2; ks++) {
            uint32_t a[4][4], b[4][2];
            // --- Blo frags, Ahi frags: acc += Ahi*Blo
            #pragma unroll
            for (int nf2 = 0; nf2 < 2; nf2++) {
                uint32_t r0, r1, r2, r3;
                ldsm_x4(st + T_BLO + boff + nf2 * (16 * ROWB) + ks * 32, r0, r1, r2, r3);
                b[nf2 * 2 + 0][0] = r0; b[nf2 * 2 + 0][1] = r1;
                b[nf2 * 2 + 1][0] = r2; b[nf2 * 2 + 1][1] = r3;
            }
            #pragma unroll
            for (int mf = 0; mf < 4; mf++)
                ldsm_x4(st + T_AHI + aoff + mf * (16 * ROWB) + ks * 32,
                        a[mf][0], a[mf][1], a[mf][2], a[mf][3]);
            #pragma unroll
            for (int mf = 0; mf < 4; mf++)
                #pragma unroll
                for (int nf = 0; nf < 4; nf++)
                    mma_bf16(acc[mf][nf], a[mf], b[nf]);
            // --- Bhi frags: acc += Ahi*Bhi
            #pragma unroll
            for (int nf2 = 0; nf2 < 2; nf2++) {
                uint32_t r0, r1, r2, r3;
                ldsm_x4(st + T_BHI + boff + nf2 * (16 * ROWB) + ks * 32, r0, r1, r2, r3);
                b[nf2 * 2 + 0][0] = r0; b[nf2 * 2 + 0][1] = r1;
                b[nf2 * 2 + 1][0] = r2; b[nf2 * 2 + 1][1] = r3;
            }
            #pragma unroll
            for (int mf = 0; mf < 4; mf++)
                #pragma unroll
                for (int nf = 0; nf < 4; nf++)
                    mma_bf16(acc[mf][nf], a[mf], b[nf]);
            // --- Alo frags: acc += Alo*Bhi
            #pragma unroll
            for (int mf = 0; mf < 4; mf++)
                ldsm_x4(st + T_ALO + aoff + mf * (16 * ROWB) + ks * 32,
                        a[mf][0], a[mf][1], a[mf][2], a[mf][3]);
            #pragma unroll
            for (int mf = 0; mf < 4; mf++)
                #pragma unroll
                for (int nf = 0; nf < 4; nf++)
                    mma_bf16(acc[mf][nf], a[mf], b[nf]);
        }
        __syncthreads();
    }

    // ---------------- epilogue -----------------------------------------------
    const int gid = lane >> 2;
    const int tig = lane & 3;
    #pragma unroll
    for (int mf = 0; mf < 4; mf++) {
        const int row0 = cy + wm * 64 + mf * 16 + gid;
        float rb0 = 0.f, rb1 = 0.f;
        if (BIAS == 2) { rb0 = bias[row0]; rb1 = bias[row0 + 8]; }
        #pragma unroll
        for (int nf = 0; nf < 4; nf++) {
            const int col = cx + wn * 32 + nf * 8 + tig * 2;
            float v0 = acc[mf][nf][0], v1 = acc[mf][nf][1];
            float v2 = acc[mf][nf][2], v3 = acc[mf][nf][3];
            if (BIAS == 1) {
                float b0 = bias[col], b1 = bias[col + 1];
                v0 += b0; v1 += b1; v2 += b0; v3 += b1;
            } else if (BIAS == 2) {
                v0 += rb0; v1 += rb0; v2 += rb1; v3 += rb1;
            }
            if (RELU) {
                v0 = fmaxf(v0, 0.f); v1 = fmaxf(v1, 0.f);
                v2 = fmaxf(v2, 0.f); v3 = fmaxf(v3, 0.f);
            }
            if (!SPLIT) {
                *(float2*)(Cf + (size_t)row0 * Nn + col)       = make_float2(v0, v1);
                *(float2*)(Cf + (size_t)(row0 + 8) * Nn + col) = make_float2(v2, v3);
            } else {
                bf16 h0 = __float2bfloat16(v0), h1 = __float2bfloat16(v1);
                bf16 h2 = __float2bfloat16(v2), h3 = __float2bfloat16(v3);
                bf16 l0 = __float2bfloat16(v0 - __bfloat162float(h0));
                bf16 l1 = __float2bfloat16(v1 - __bfloat162float(h1));
                bf16 l2 = __float2bfloat16(v2 - __bfloat162float(h2));
                bf16 l3 = __float2bfloat16(v3 - __bfloat162float(h3));
                __nv_bfloat162 hp0; hp0.x = h0; hp0.y = h1;
                __nv_bfloat162 hp1; hp1.x = h2; hp1.y = h3;
                __nv_bfloat162 lp0; lp0.x = l0; lp0.y = l1;
                __nv_bfloat162 lp1; lp1.x = l2; lp1.y = l3;
                *(__nv_bfloat162*)(Chi + (size_t)row0 * Nn + col)       = hp0;
                *(__nv_bfloat162*)(Chi + (size_t)(row0 + 8) * Nn + col) = hp1;
                *(__nv_bfloat162*)(Clo + (size_t)row0 * Nn + col)       = lp0;
                *(__nv_bfloat162*)(Clo + (size_t)(row0 + 8) * Nn + col) = lp1;
            }
        }
    }
}

// ---------------- positional encoding ----------------------------------------
__device__ __forceinline__ float pe_val(int pos, int j) {
    float even  = (float)(j & ~1);
    float denom = powf(10000.0f, even * (1.0f / (float)DD));
    float arg   = (float)pos / denom;
    return (j & 1) ? cosf(arg) : sinf(arg);
}

// ---------------- elementwise kernels -----------------------------------------
__global__ void zero_kernel(float* p, int n) {
    int i = blockIdx.x * blockDim.x + threadIdx.x;
    if (i < n) p[i] = 0.0f;
}

#define CS_ROWS 128
__global__ void colsum_kernel(const float* __restrict__ X, float* __restrict__ colsum) {
    int j  = blockIdx.x * blockDim.x + threadIdx.x;
    int r0 = blockIdx.y * CS_ROWS;
    float s = 0.0f;
    #pragma unroll 4
    for (int i = 0; i < CS_ROWS; i++) {
        int pos = r0 + i;
        s += pe_val(pos, j) * X[(size_t)pos * DD + j];
    }
    atomicAdd(&colsum[j], s);
}

__device__ __forceinline__ void split_store(bf16* hi, bf16* lo, size_t idx, float v) {
    bf16 h = __float2bfloat16(v);
    hi[idx] = h;
    lo[idx] = __float2bfloat16(v - __bfloat162float(h));
}

// loo = (colsum - PE*X)/(N-1) -> split bf16, plus split of X itself
__global__ void loo_split_kernel(const float* __restrict__ X,
                                 const float* __restrict__ colsum,
                                 bf16* __restrict__ lhi, bf16* __restrict__ llo,
                                 bf16* __restrict__ xhi, bf16* __restrict__ xlo) {
    int idx = blockIdx.x * blockDim.x + threadIdx.x;   // over N*D
    int row = idx >> 10;
    int j   = idx & 1023;
    float x = X[idx];
    split_store(xhi, xlo, idx, x);
    float e = pe_val(row, j) * x;
    float v = (colsum[j] - e) * (1.0f / (float)(NN - 1));
    split_store(lhi, llo, idx, v);
}

// transpose + split: src [R][C] fp32 -> dst [C][R] bf16 hi/lo
__global__ void tsplit_kernel(const float* __restrict__ src,
                              bf16* __restrict__ dhi, bf16* __restrict__ dlo,
                              int R, int C) {
    __shared__ float t[32][33];
    int bx = blockIdx.x * 32;
    int by = blockIdx.y * 32;
    int tx = threadIdx.x, ty = threadIdx.y;
    #pragma unroll
    for (int i = 0; i < 4; i++)
        t[ty + i * 8][tx] = src[(size_t)(by + ty + i * 8) * C + bx + tx];
    __syncthreads();
    #pragma unroll
    for (int i = 0; i < 4; i++) {
        float v = t[tx][ty + i * 8];
        split_store(dhi, dlo, (size_t)(bx + ty + i * 8) * R + by + tx, v);
    }
}

// row softmax over scores; writes att split bf16
__global__ void softmax_split_kernel(float* __restrict__ S,
                                     bf16* __restrict__ ahi, bf16* __restrict__ alo, int n) {
    __shared__ float red[8];
    float* row = S + (size_t)blockIdx.x * n;
    int tid = threadIdx.x;
    int lane = tid & 31, warp = tid >> 5;

    float m = -1e30f;
    for (int j = tid; j < n; j += 256) m = fmaxf(m, row[j]);
    #pragma unroll
    for (int o = 16; o > 0; o >>= 1) m = fmaxf(m, __shfl_xor_sync(0xffffffffu, m, o));
    if (lane == 0) red[warp] = m;
    __syncthreads();
    if (tid < 8) {
        float v = red[tid];
        #pragma unroll
        for (int o = 4; o > 0; o >>= 1) v = fmaxf(v, __shfl_xor_sync(0xffu, v, o));
        if (tid == 0) red[0] = v;
    }
    __syncthreads();
    m = red[0];
    __syncthreads();

    float s = 0.0f;
    for (int j = tid; j < n; j += 256) {
        float e = __expf(row[j] - m);
        row[j] = e;
        s += e;
    }
    #pragma unroll
    for (int o = 16; o > 0; o >>= 1) s += __shfl_xor_sync(0xffffffffu, s, o);
    if (lane == 0) red[warp] = s;
    __syncthreads();
    if (tid < 8) {
        float v = red[tid];
        #pragma unroll
        for (int o = 4; o > 0; o >>= 1) v += __shfl_xor_sync(0xffu, v, o);
        if (tid == 0) red[0] = v;
    }
    __syncthreads();
    float inv = 1.0f / red[0];
    size_t base = (size_t)blockIdx.x * n;
    for (int j = tid; j < n; j += 256) {
        float a = row[j] * inv;
        split_store(ahi, alo, base + j, a);
    }
}

// ---------------- driver ------------------------------------------------------
extern "C" void kernel_launch(void* const* d_in, const int* in_sizes, int n_in,
                              void* d_out, int out_size) {
    const float* X  = (const float*)d_in[0];
    const float* Wv = (const float*)d_in[2];
    const float* bv = (const float*)d_in[3];
    const float* W1 = (const float*)d_in[4];
    const float* b1 = (const float*)d_in[5];
    const float* W2 = (const float*)d_in[6];
    const float* b2 = (const float*)d_in[7];
    float* out = (float*)d_out;

    void* p;
    cudaGetSymbolAddress(&p, g_colsum); float* colsum = (float*)p;
    cudaGetSymbolAddress(&p, g_scores); float* scores = (float*)p;
    cudaGetSymbolAddress(&p, g_Xhi);    bf16* Xhi   = (bf16*)p;
    cudaGetSymbolAddress(&p, g_Xlo);    bf16* Xlo   = (bf16*)p;
    cudaGetSymbolAddress(&p, g_loohi);  bf16* loohi = (bf16*)p;
    cudaGetSymbolAddress(&p, g_loolo);  bf16* loolo = (bf16*)p;
    cudaGetSymbolAddress(&p, g_WvThi);  bf16* WvThi = (bf16*)p;
    cudaGetSymbolAddress(&p, g_WvTlo);  bf16* WvTlo = (bf16*)p;
    cudaGetSymbolAddress(&p, g_W1Thi);  bf16* W1Thi = (bf16*)p;
    cudaGetSymbolAddress(&p, g_W1Tlo);  bf16* W1Tlo = (bf16*)p;
    cudaGetSymbolAddress(&p, g_hidhi);  bf16* hdhi  = (bf16*)p;
    cudaGetSymbolAddress(&p, g_hidlo);  bf16* hdlo  = (bf16*)p;
    cudaGetSymbolAddress(&p, g_W2Thi);  bf16* W2Thi = (bf16*)p;
    cudaGetSymbolAddress(&p, g_W2Tlo);  bf16* W2Tlo = (bf16*)p;
    cudaGetSymbolAddress(&p, g_atthi);  bf16* athi  = (bf16*)p;
    cudaGetSymbolAddress(&p, g_attlo);  bf16* atlo  = (bf16*)p;
    cudaGetSymbolAddress(&p, g_VThi);   bf16* VThi  = (bf16*)p;
    cudaGetSymbolAddress(&p, g_VTlo);   bf16* VTlo  = (bf16*)p;

    cudaFuncSetAttribute(gemm_mma<1, false, false>,
                         cudaFuncAttributeMaxDynamicSharedMemorySize, GSMEM);
    cudaFuncSetAttribute(gemm_mma<1, true,  true>,
                         cudaFuncAttributeMaxDynamicSharedMemorySize, GSMEM);
    cudaFuncSetAttribute(gemm_mma<0, false, false>,
                         cudaFuncAttributeMaxDynamicSharedMemorySize, GSMEM);
    cudaFuncSetAttribute(gemm_mma<2, false, true>,
                         cudaFuncAttributeMaxDynamicSharedMemorySize, GSMEM);

    // --- operand prep --------------------------------------------------------
    zero_kernel<<<4, 256>>>(colsum, DD);
    colsum_kernel<<<dim3(DD / 256, NN / CS_ROWS), 256>>>(X, colsum);
    loo_split_kernel<<<(NN * DD) / 256, 256>>>(X, colsum, loohi, loolo, Xhi, Xlo);
    tsplit_kernel<<<dim3(DD / 32, DD / 32),     dim3(32, 8)>>>(Wv, WvThi, WvTlo, DD, DD);
    tsplit_kernel<<<dim3(HH / 32, (2*DD) / 32), dim3(32, 8)>>>(W1, W1Thi, W1Tlo, 2 * DD, HH);
    tsplit_kernel<<<dim3(NN / 32, HH / 32),     dim3(32, 8)>>>(W2, W2Thi, W2Tlo, HH, NN);

    // --- GEMM1 (transposed): VT = WvT @ X^T + bv(row)  (M=1024, N=4096, K=1024)
    gemm_mma<2, false, true><<<dim3(NN / BN, DD / BM), 256, GSMEM>>>(
        WvThi, WvTlo, WvThi, WvTlo, Xhi, Xlo, bv,
        nullptr, VThi, VTlo, NN, DD, DD);

    // --- GEMM2: hidden = relu([X|loo] @ W1 + b1) (4096,2048,K=2048,K1=1024) --
    gemm_mma<1, true, true><<<dim3(HH / BN, NN / BM), 256, GSMEM>>>(
        Xhi, Xlo, loohi, loolo, W1Thi, W1Tlo, b1,
        nullptr, hdhi, hdlo, HH, 2 * DD, DD);

    // --- GEMM3: scores = hidden @ W2 + b2 (4096,4096,2048) -------------------
    gemm_mma<1, false, false><<<dim3(NN / BN, NN / BM), 256, GSMEM>>>(
        hdhi, hdlo, hdhi, hdlo, W2Thi, W2Tlo, b2,
        scores, nullptr, nullptr, NN, HH, HH);

    // --- softmax -> att split -------------------------------------------------
    softmax_split_kernel<<<NN, 256>>>(scores, athi, atlo, NN);

    // --- GEMM4: out = att @ V (4096,1024,4096) --------------------------------
    gemm_mma<0, false, false><<<dim3(DD / BN, NN / BM), 256, GSMEM>>>(
        athi, atlo, athi, atlo, VThi, VTlo, nullptr,
        out, nullptr, nullptr, DD, NN, NN);
}

// round 8
// speedup vs baseline: 1.4147x; 1.1667x over previous
#include <cuda_runtime.h>
#include <cuda_bf16.h>
#include <math.h>
#include <stdint.h>

// Problem constants
#define NN 4096
#define DD 1024
#define HH 2048

typedef __nv_bfloat16 bf16;

// ---------------- scratch (device globals; no allocations allowed) ----------
__device__ float g_colsum[DD];
__device__ float g_scores[(size_t)NN * NN];            // 64 MB

__device__ bf16 g_Xhi[(size_t)NN * DD],     g_Xlo[(size_t)NN * DD];
__device__ bf16 g_loohi[(size_t)NN * DD],   g_loolo[(size_t)NN * DD];
__device__ bf16 g_WvThi[(size_t)DD * DD],   g_WvTlo[(size_t)DD * DD];
__device__ bf16 g_W1Thi[(size_t)HH * 2*DD], g_W1Tlo[(size_t)HH * 2*DD];
__device__ bf16 g_hidhi[(size_t)NN * HH],   g_hidlo[(size_t)NN * HH];
__device__ bf16 g_W2Thi[(size_t)NN * HH],   g_W2Tlo[(size_t)NN * HH];
__device__ bf16 g_atthi[(size_t)NN * NN],   g_attlo[(size_t)NN * NN];
__device__ bf16 g_VThi[(size_t)DD * NN],    g_VTlo[(size_t)DD * NN];

// ---------------- helpers -----------------------------------------------------
__device__ __forceinline__ uint32_t smem_u32(const void* p) {
    uint32_t a;
    asm("{ .reg .u64 t; cvta.to.shared.u64 t, %1; cvt.u32.u64 %0, t; }" : "=r"(a) : "l"(p));
    return a;
}
__device__ __forceinline__ void cp_async16(uint32_t saddr, const void* gaddr) {
    asm volatile("cp.async.cg.shared.global [%0], [%1], 16;" :: "r"(saddr), "l"(gaddr));
}
__device__ __forceinline__ void cp_commit() {
    asm volatile("cp.async.commit_group;");
}
template<int N>
__device__ __forceinline__ void cp_wait() {
    asm volatile("cp.async.wait_group %0;" :: "n"(N));
}
__device__ __forceinline__ void ldsm_x4(uint32_t addr, uint32_t& r0, uint32_t& r1,
                                        uint32_t& r2, uint32_t& r3) {
    asm volatile("ldmatrix.sync.aligned.m8n8.x4.shared.b16 {%0,%1,%2,%3}, [%4];"
                 : "=r"(r0), "=r"(r1), "=r"(r2), "=r"(r3) : "r"(addr));
}
__device__ __forceinline__ void mma_bf16(float* c, const uint32_t* a, const uint32_t* b) {
    asm volatile(
        "mma.sync.aligned.m16n8k16.row.col.f32.bf16.bf16.f32 "
        "{%0,%1,%2,%3}, {%4,%5,%6,%7}, {%8,%9}, {%0,%1,%2,%3};"
        : "+f"(c[0]), "+f"(c[1]), "+f"(c[2]), "+f"(c[3])
        : "r"(a[0]), "r"(a[1]), "r"(a[2]), "r"(a[3]), "r"(b[0]), "r"(b[1]));
}

// ---------------- GEMM: C(M,N) = [A|A2] @ B'^T, fused bf16x3 ------------------
// smem layout: 64B rows (32 bf16), XOR swizzle: unit' = unit ^ ((row>>1)&3).
#define BM 128
#define BN 128
#define BK 32
#define TILE (BM * 64)               // 8192 B
#define T_AHI 0
#define T_ALO TILE
#define T_BHI (2 * TILE)
#define T_BLO (3 * TILE)
#define STAGE_BYTES (4 * TILE)       // 32768 B
#define STAGES 3
#define GSMEM (STAGES * STAGE_BYTES) // 98304 B

__device__ __forceinline__ uint32_t swz(int r, int q) {
    return (uint32_t)(r * 64 + ((q ^ ((r >> 1) & 3)) << 4));
}

__device__ __forceinline__ void load_chunk(uint32_t sstage,
                                           const bf16* __restrict__ Ahi,
                                           const bf16* __restrict__ Alo, int sA, int ka,
                                           const bf16* __restrict__ Bhi,
                                           const bf16* __restrict__ Blo, int sB, int kb,
                                           int cy, int cx, int tid) {
    #pragma unroll
    for (int i = 0; i < 2; i++) {
        int u = tid + i * 256;       // 0..511
        int r = u >> 2, q = u & 3;
        uint32_t so = swz(r, q);
        size_t ga = (size_t)(cy + r) * sA + ka + q * 8;
        size_t gb = (size_t)(cx + r) * sB + kb + q * 8;
        cp_async16(sstage + T_AHI + so, Ahi + ga);
        cp_async16(sstage + T_ALO + so, Alo + ga);
        cp_async16(sstage + T_BHI + so, Bhi + gb);
        cp_async16(sstage + T_BLO + so, Blo + gb);
    }
}

// BIAS: 0=none, 1=per-column, 2=per-row
template<int BIAS, bool RELU, bool SPLIT>
__global__ __launch_bounds__(256, 2)
void gemm_mma(const bf16* __restrict__ Ahi,  const bf16* __restrict__ Alo,
              const bf16* __restrict__ A2hi, const bf16* __restrict__ A2lo,
              const bf16* __restrict__ Bhi,  const bf16* __restrict__ Blo,
              const float* __restrict__ bias,
              float* __restrict__ Cf, bf16* __restrict__ Chi, bf16* __restrict__ Clo,
              int Nn, int K, int K1) {
    extern __shared__ char smem[];
    const uint32_t sb = smem_u32(smem);
    const int tid  = threadIdx.x;
    const int lane = tid & 31;
    const int wid  = tid >> 5;
    const int wm   = wid >> 2;          // 0..1  (M)
    const int wn   = wid & 3;           // 0..3  (N)
    const int cx   = blockIdx.x * BN;
    const int cy   = blockIdx.y * BM;
    const int K2   = K - K1;
    const int NCK  = K >> 5;

    float acc[4][4][4];
    #pragma unroll
    for (int i = 0; i < 4; i++)
        #pragma unroll
        for (int j = 0; j < 4; j++)
            #pragma unroll
            for (int k = 0; k < 4; k++) acc[i][j][k] = 0.0f;

    // per-lane fragment base offsets (swizzle folded in), per ks
    const int arow = wm * 64 + (lane & 15);
    const int abit = (lane >> 4) & 1;
    const int asw  = (arow >> 1) & 3;
    const int brow = wn * 32 + (lane & 7) + ((lane & 16) ? 8 : 0);
    const int bbit = (lane >> 3) & 1;
    const int bsw  = (brow >> 1) & 3;
    uint32_t aofk[2], bofk[2];
    #pragma unroll
    for (int ks = 0; ks < 2; ks++) {
        aofk[ks] = (uint32_t)(arow * 64 + ((((ks << 1) | abit) ^ asw) << 4));
        bofk[ks] = (uint32_t)(brow * 64 + ((((ks << 1) | bbit) ^ bsw) << 4));
    }

    // prefetch chunks 0,1
    #pragma unroll
    for (int c = 0; c < STAGES - 1 && c < 64; c++) {
        if (c < NCK) {
            int k = c * BK;
            const bf16 *Ah, *Al; int ka, sA;
            if (k < K1) { Ah = Ahi;  Al = Alo;  ka = k;      sA = K1; }
            else        { Ah = A2hi; Al = A2lo; ka = k - K1; sA = K2; }
            load_chunk(sb + c * STAGE_BYTES, Ah, Al, sA, ka, Bhi, Blo, K, k, cy, cx, tid);
        }
        cp_commit();
    }

    int bufc = 0;
    for (int c = 0; c < NCK; c++) {
        if (c == NCK - 1) cp_wait<0>(); else cp_wait<1>();
        __syncthreads();
        // issue chunk c+2 into buffer (c+2)%3 (previous consumer finished: sync above)
        if (c + 2 < NCK) {
            int k = (c + 2) * BK;
            const bf16 *Ah, *Al; int ka, sA;
            if (k < K1) { Ah = Ahi;  Al = Alo;  ka = k;      sA = K1; }
            else        { Ah = A2hi; Al = A2lo; ka = k - K1; sA = K2; }
            int nb = bufc + 2; if (nb >= STAGES) nb -= STAGES;
            load_chunk(sb + nb * STAGE_BYTES, Ah, Al, sA, ka, Bhi, Blo, K, k, cy, cx, tid);
            cp_commit();
        }

        const uint32_t st = sb + bufc * STAGE_BYTES;
        bufc++; if (bufc >= STAGES) bufc = 0;

        #pragma unroll
        for (int ks = 0; ks < 2; ks++) {
            uint32_t a[4][4], b[4][2];
            // --- acc += Ahi*Blo
            #pragma unroll
            for (int nf2 = 0; nf2 < 2; nf2++) {
                uint32_t r0, r1, r2, r3;
                ldsm_x4(st + T_BLO + bofk[ks] + nf2 * 1024, r0, r1, r2, r3);
                b[nf2 * 2 + 0][0] = r0; b[nf2 * 2 + 0][1] = r1;
                b[nf2 * 2 + 1][0] = r2; b[nf2 * 2 + 1][1] = r3;
            }
            #pragma unroll
            for (int mf = 0; mf < 4; mf++)
                ldsm_x4(st + T_AHI + aofk[ks] + mf * 1024,
                        a[mf][0], a[mf][1], a[mf][2], a[mf][3]);
            #pragma unroll
            for (int mf = 0; mf < 4; mf++)
                #pragma unroll
                for (int nf = 0; nf < 4; nf++)
                    mma_bf16(acc[mf][nf], a[mf], b[nf]);
            // --- acc += Ahi*Bhi
            #pragma unroll
            for (int nf2 = 0; nf2 < 2; nf2++) {
                uint32_t r0, r1, r2, r3;
                ldsm_x4(st + T_BHI + bofk[ks] + nf2 * 1024, r0, r1, r2, r3);
                b[nf2 * 2 + 0][0] = r0; b[nf2 * 2 + 0][1] = r1;
                b[nf2 * 2 + 1][0] = r2; b[nf2 * 2 + 1][1] = r3;
            }
            #pragma unroll
            for (int mf = 0; mf < 4; mf++)
                #pragma unroll
                for (int nf = 0; nf < 4; nf++)
                    mma_bf16(acc[mf][nf], a[mf], b[nf]);
            // --- acc += Alo*Bhi
            #pragma unroll
            for (int mf = 0; mf < 4; mf++)
                ldsm_x4(st + T_ALO + aofk[ks] + mf * 1024,
                        a[mf][0], a[mf][1], a[mf][2], a[mf][3]);
            #pragma unroll
            for (int mf = 0; mf < 4; mf++)
                #pragma unroll
                for (int nf = 0; nf < 4; nf++)
                    mma_bf16(acc[mf][nf], a[mf], b[nf]);
        }
        __syncthreads();
    }

    // ---------------- epilogue -----------------------------------------------
    const int gid = lane >> 2;
    const int tig = lane & 3;
    #pragma unroll
    for (int mf = 0; mf < 4; mf++) {
        const int row0 = cy + wm * 64 + mf * 16 + gid;
        float rb0 = 0.f, rb1 = 0.f;
        if (BIAS == 2) { rb0 = bias[row0]; rb1 = bias[row0 + 8]; }
        #pragma unroll
        for (int nf = 0; nf < 4; nf++) {
            const int col = cx + wn * 32 + nf * 8 + tig * 2;
            float v0 = acc[mf][nf][0], v1 = acc[mf][nf][1];
            float v2 = acc[mf][nf][2], v3 = acc[mf][nf][3];
            if (BIAS == 1) {
                float b0 = bias[col], b1 = bias[col + 1];
                v0 += b0; v1 += b1; v2 += b0; v3 += b1;
            } else if (BIAS == 2) {
                v0 += rb0; v1 += rb0; v2 += rb1; v3 += rb1;
            }
            if (RELU) {
                v0 = fmaxf(v0, 0.f); v1 = fmaxf(v1, 0.f);
                v2 = fmaxf(v2, 0.f); v3 = fmaxf(v3, 0.f);
            }
            if (!SPLIT) {
                *(float2*)(Cf + (size_t)row0 * Nn + col)       = make_float2(v0, v1);
                *(float2*)(Cf + (size_t)(row0 + 8) * Nn + col) = make_float2(v2, v3);
            } else {
                bf16 h0 = __float2bfloat16(v0), h1 = __float2bfloat16(v1);
                bf16 h2 = __float2bfloat16(v2), h3 = __float2bfloat16(v3);
                bf16 l0 = __float2bfloat16(v0 - __bfloat162float(h0));
                bf16 l1 = __float2bfloat16(v1 - __bfloat162float(h1));
                bf16 l2 = __float2bfloat16(v2 - __bfloat162float(h2));
                bf16 l3 = __float2bfloat16(v3 - __bfloat162float(h3));
                __nv_bfloat162 hp0; hp0.x = h0; hp0.y = h1;
                __nv_bfloat162 hp1; hp1.x = h2; hp1.y = h3;
                __nv_bfloat162 lp0; lp0.x = l0; lp0.y = l1;
                __nv_bfloat162 lp1; lp1.x = l2; lp1.y = l3;
                *(__nv_bfloat162*)(Chi + (size_t)row0 * Nn + col)       = hp0;
                *(__nv_bfloat162*)(Chi + (size_t)(row0 + 8) * Nn + col) = hp1;
                *(__nv_bfloat162*)(Clo + (size_t)row0 * Nn + col)       = lp0;
                *(__nv_bfloat162*)(Clo + (size_t)(row0 + 8) * Nn + col) = lp1;
            }
        }
    }
}

// ---------------- positional encoding ----------------------------------------
__device__ __forceinline__ float pe_val(int pos, int j) {
    float even  = (float)(j & ~1);
    float denom = powf(10000.0f, even * (1.0f / (float)DD));
    float arg   = (float)pos / denom;
    return (j & 1) ? cosf(arg) : sinf(arg);
}

// ---------------- elementwise kernels -----------------------------------------
__global__ void zero_kernel(float* p, int n) {
    int i = blockIdx.x * blockDim.x + threadIdx.x;
    if (i < n) p[i] = 0.0f;
}

#define CS_ROWS 128
__global__ void colsum_kernel(const float* __restrict__ X, float* __restrict__ colsum) {
    int j  = blockIdx.x * blockDim.x + threadIdx.x;
    int r0 = blockIdx.y * CS_ROWS;
    float s = 0.0f;
    #pragma unroll 4
    for (int i = 0; i < CS_ROWS; i++) {
        int pos = r0 + i;
        s += pe_val(pos, j) * X[(size_t)pos * DD + j];
    }
    atomicAdd(&colsum[j], s);
}

__device__ __forceinline__ void split_store(bf16* hi, bf16* lo, size_t idx, float v) {
    bf16 h = __float2bfloat16(v);
    hi[idx] = h;
    lo[idx] = __float2bfloat16(v - __bfloat162float(h));
}

// loo = (colsum - PE*X)/(N-1) -> split bf16, plus split of X itself
__global__ void loo_split_kernel(const float* __restrict__ X,
                                 const float* __restrict__ colsum,
                                 bf16* __restrict__ lhi, bf16* __restrict__ llo,
                                 bf16* __restrict__ xhi, bf16* __restrict__ xlo) {
    int idx = blockIdx.x * blockDim.x + threadIdx.x;   // over N*D
    int row = idx >> 10;
    int j   = idx & 1023;
    float x = X[idx];
    split_store(xhi, xlo, idx, x);
    float e = pe_val(row, j) * x;
    float v = (colsum[j] - e) * (1.0f / (float)(NN - 1));
    split_store(lhi, llo, idx, v);
}

// transpose + split: src [R][C] fp32 -> dst [C][R] bf16 hi/lo
__global__ void tsplit_kernel(const float* __restrict__ src,
                              bf16* __restrict__ dhi, bf16* __restrict__ dlo,
                              int R, int C) {
    __shared__ float t[32][33];
    int bx = blockIdx.x * 32;
    int by = blockIdx.y * 32;
    int tx = threadIdx.x, ty = threadIdx.y;
    #pragma unroll
    for (int i = 0; i < 4; i++)
        t[ty + i * 8][tx] = src[(size_t)(by + ty + i * 8) * C + bx + tx];
    __syncthreads();
    #pragma unroll
    for (int i = 0; i < 4; i++) {
        float v = t[tx][ty + i * 8];
        split_store(dhi, dlo, (size_t)(bx + ty + i * 8) * R + by + tx, v);
    }
}

// row softmax over scores; writes att split bf16
__global__ void softmax_split_kernel(float* __restrict__ S,
                                     bf16* __restrict__ ahi, bf16* __restrict__ alo, int n) {
    __shared__ float red[8];
    float* row = S + (size_t)blockIdx.x * n;
    int tid = threadIdx.x;
    int lane = tid & 31, warp = tid >> 5;

    float m = -1e30f;
    for (int j = tid; j < n; j += 256) m = fmaxf(m, row[j]);
    #pragma unroll
    for (int o = 16; o > 0; o >>= 1) m = fmaxf(m, __shfl_xor_sync(0xffffffffu, m, o));
    if (lane == 0) red[warp] = m;
    __syncthreads();
    if (tid < 8) {
        float v = red[tid];
        #pragma unroll
        for (int o = 4; o > 0; o >>= 1) v = fmaxf(v, __shfl_xor_sync(0xffu, v, o));
        if (tid == 0) red[0] = v;
    }
    __syncthreads();
    m = red[0];
    __syncthreads();

    float s = 0.0f;
    for (int j = tid; j < n; j += 256) {
        float e = __expf(row[j] - m);
        row[j] = e;
        s += e;
    }
    #pragma unroll
    for (int o = 16; o > 0; o >>= 1) s += __shfl_xor_sync(0xffffffffu, s, o);
    if (lane == 0) red[warp] = s;
    __syncthreads();
    if (tid < 8) {
        float v = red[tid];
        #pragma unroll
        for (int o = 4; o > 0; o >>= 1) v += __shfl_xor_sync(0xffu, v, o);
        if (tid == 0) red[0] = v;
    }
    __syncthreads();
    float inv = 1.0f / red[0];
    size_t base = (size_t)blockIdx.x * n;
    for (int j = tid; j < n; j += 256) {
        float a = row[j] * inv;
        split_store(ahi, alo, base + j, a);
    }
}

// ---------------- driver ------------------------------------------------------
extern "C" void kernel_launch(void* const* d_in, const int* in_sizes, int n_in,
                              void* d_out, int out_size) {
    const float* X  = (const float*)d_in[0];
    const float* Wv = (const float*)d_in[2];
    const float* bv = (const float*)d_in[3];
    const float* W1 = (const float*)d_in[4];
    const float* b1 = (const float*)d_in[5];
    const float* W2 = (const float*)d_in[6];
    const float* b2 = (const float*)d_in[7];
    float* out = (float*)d_out;

    void* p;
    cudaGetSymbolAddress(&p, g_colsum); float* colsum = (float*)p;
    cudaGetSymbolAddress(&p, g_scores); float* scores = (float*)p;
    cudaGetSymbolAddress(&p, g_Xhi);    bf16* Xhi   = (bf16*)p;
    cudaGetSymbolAddress(&p, g_Xlo);    bf16* Xlo   = (bf16*)p;
    cudaGetSymbolAddress(&p, g_loohi);  bf16* loohi = (bf16*)p;
    cudaGetSymbolAddress(&p, g_loolo);  bf16* loolo = (bf16*)p;
    cudaGetSymbolAddress(&p, g_WvThi);  bf16* WvThi = (bf16*)p;
    cudaGetSymbolAddress(&p, g_WvTlo);  bf16* WvTlo = (bf16*)p;
    cudaGetSymbolAddress(&p, g_W1Thi);  bf16* W1Thi = (bf16*)p;
    cudaGetSymbolAddress(&p, g_W1Tlo);  bf16* W1Tlo = (bf16*)p;
    cudaGetSymbolAddress(&p, g_hidhi);  bf16* hdhi  = (bf16*)p;
    cudaGetSymbolAddress(&p, g_hidlo);  bf16* hdlo  = (bf16*)p;
    cudaGetSymbolAddress(&p, g_W2Thi);  bf16* W2Thi = (bf16*)p;
    cudaGetSymbolAddress(&p, g_W2Tlo);  bf16* W2Tlo = (bf16*)p;
    cudaGetSymbolAddress(&p, g_atthi);  bf16* athi  = (bf16*)p;
    cudaGetSymbolAddress(&p, g_attlo);  bf16* atlo  = (bf16*)p;
    cudaGetSymbolAddress(&p, g_VThi);   bf16* VThi  = (bf16*)p;
    cudaGetSymbolAddress(&p, g_VTlo);   bf16* VTlo  = (bf16*)p;

    cudaFuncSetAttribute(gemm_mma<1, false, false>,
                         cudaFuncAttributeMaxDynamicSharedMemorySize, GSMEM);
    cudaFuncSetAttribute(gemm_mma<1, true,  true>,
                         cudaFuncAttributeMaxDynamicSharedMemorySize, GSMEM);
    cudaFuncSetAttribute(gemm_mma<0, false, false>,
                         cudaFuncAttributeMaxDynamicSharedMemorySize, GSMEM);
    cudaFuncSetAttribute(gemm_mma<2, false, true>,
                         cudaFuncAttributeMaxDynamicSharedMemorySize, GSMEM);

    // --- operand prep --------------------------------------------------------
    zero_kernel<<<4, 256>>>(colsum, DD);
    colsum_kernel<<<dim3(DD / 256, NN / CS_ROWS), 256>>>(X, colsum);
    loo_split_kernel<<<(NN * DD) / 256, 256>>>(X, colsum, loohi, loolo, Xhi, Xlo);
    tsplit_kernel<<<dim3(DD / 32, DD / 32),     dim3(32, 8)>>>(Wv, WvThi, WvTlo, DD, DD);
    tsplit_kernel<<<dim3(HH / 32, (2*DD) / 32), dim3(32, 8)>>>(W1, W1Thi, W1Tlo, 2 * DD, HH);
    tsplit_kernel<<<dim3(NN / 32, HH / 32),     dim3(32, 8)>>>(W2, W2Thi, W2Tlo, HH, NN);

    // --- GEMM1 (transposed): VT = WvT @ X^T + bv(row)  (M=1024, N=4096, K=1024)
    gemm_mma<2, false, true><<<dim3(NN / BN, DD / BM), 256, GSMEM>>>(
        WvThi, WvTlo, WvThi, WvTlo, Xhi, Xlo, bv,
        nullptr, VThi, VTlo, NN, DD, DD);

    // --- GEMM2: hidden = relu([X|loo] @ W1 + b1) (4096,2048,K=2048,K1=1024) --
    gemm_mma<1, true, true><<<dim3(HH / BN, NN / BM), 256, GSMEM>>>(
        Xhi, Xlo, loohi, loolo, W1Thi, W1Tlo, b1,
        nullptr, hdhi, hdlo, HH, 2 * DD, DD);

    // --- GEMM3: scores = hidden @ W2 + b2 (4096,4096,2048) -------------------
    gemm_mma<1, false, false><<<dim3(NN / BN, NN / BM), 256, GSMEM>>>(
        hdhi, hdlo, hdhi, hdlo, W2Thi, W2Tlo, b2,
        scores, nullptr, nullptr, NN, HH, HH);

    // --- softmax -> att split -------------------------------------------------
    softmax_split_kernel<<<NN, 256>>>(scores, athi, atlo, NN);

    // --- GEMM4: out = att @ V (4096,1024,4096) --------------------------------
    gemm_mma<0, false, false><<<dim3(DD / BN, NN / BM), 256, GSMEM>>>(
        athi, atlo, athi, atlo, VThi, VTlo, nullptr,
        out, nullptr, nullptr, DD, NN, NN);
}

// round 9
// speedup vs baseline: 1.4152x; 1.0003x over previous
#include <cuda_runtime.h>
#include <cuda_bf16.h>
#include <math.h>
#include <stdint.h>

// Problem constants
#define NN 4096
#define DD 1024
#define HH 2048

typedef __nv_bfloat16 bf16;

// ---------------- scratch (device globals; no allocations allowed) ----------
__device__ float g_invden[DD / 2];
__device__ float g_scoresA[(size_t)NN * NN];           // 64 MB
__device__ float g_scoresB[(size_t)NN * NN];           // 64 MB

__device__ bf16 g_Xhi[(size_t)NN * DD],     g_Xlo[(size_t)NN * DD];
__device__ bf16 g_loohi[(size_t)NN * DD],   g_loolo[(size_t)NN * DD];
__device__ bf16 g_WvThi[(size_t)DD * DD],   g_WvTlo[(size_t)DD * DD];
__device__ bf16 g_W1Thi[(size_t)HH * 2*DD], g_W1Tlo[(size_t)HH * 2*DD];
__device__ bf16 g_hidhi[(size_t)NN * HH],   g_hidlo[(size_t)NN * HH];
__device__ bf16 g_W2Thi[(size_t)NN * HH],   g_W2Tlo[(size_t)NN * HH];
__device__ bf16 g_atthi[(size_t)NN * NN],   g_attlo[(size_t)NN * NN];
__device__ bf16 g_VThi[(size_t)DD * NN],    g_VTlo[(size_t)DD * NN];
__device__ float g_colsum[DD];

// ---------------- helpers -----------------------------------------------------
__device__ __forceinline__ uint32_t smem_u32(const void* p) {
    uint32_t a;
    asm("{ .reg .u64 t; cvta.to.shared.u64 t, %1; cvt.u32.u64 %0, t; }" : "=r"(a) : "l"(p));
    return a;
}
__device__ __forceinline__ void cp_async16(uint32_t saddr, const void* gaddr) {
    asm volatile("cp.async.cg.shared.global [%0], [%1], 16;" :: "r"(saddr), "l"(gaddr));
}
__device__ __forceinline__ void cp_commit() {
    asm volatile("cp.async.commit_group;");
}
template<int N>
__device__ __forceinline__ void cp_wait() {
    asm volatile("cp.async.wait_group %0;" :: "n"(N));
}
__device__ __forceinline__ void ldsm_x4(uint32_t addr, uint32_t& r0, uint32_t& r1,
                                        uint32_t& r2, uint32_t& r3) {
    asm volatile("ldmatrix.sync.aligned.m8n8.x4.shared.b16 {%0,%1,%2,%3}, [%4];"
                 : "=r"(r0), "=r"(r1), "=r"(r2), "=r"(r3) : "r"(addr));
}
__device__ __forceinline__ void mma_bf16(float* c, const uint32_t* a, const uint32_t* b) {
    asm volatile(
        "mma.sync.aligned.m16n8k16.row.col.f32.bf16.bf16.f32 "
        "{%0,%1,%2,%3}, {%4,%5,%6,%7}, {%8,%9}, {%0,%1,%2,%3};"
        : "+f"(c[0]), "+f"(c[1]), "+f"(c[2]), "+f"(c[3])
        : "r"(a[0]), "r"(a[1]), "r"(a[2]), "r"(a[3]), "r"(b[0]), "r"(b[1]));
}

// ---------------- unified GEMM job description --------------------------------
struct GP {
    const bf16 *Ahi, *Alo, *A2hi, *A2lo;   // A row-major [M][ldA]; A2 for k>=K1
    const bf16 *Bhi, *Blo;                 // B' row-major [N][ldB]
    const float* bias;
    float* Cf;
    bf16 *Chi, *Clo;
    int gx;                                // tiles along N
    int ldA1, ldA2, ldB, ldC;
    int Kloop, K1;
    int biasmode;                          // 0 none, 1 per-col, 2 per-row
    int relu, split;
};

#define BM 128
#define BN 128
#define BK 32
#define TILE (BM * 64)               // 8192 B
#define T_AHI 0
#define T_ALO TILE
#define T_BHI (2 * TILE)
#define T_BLO (3 * TILE)
#define STAGE_BYTES (4 * TILE)       // 32768 B
#define STAGES 3
#define GSMEM (STAGES * STAGE_BYTES) // 98304 B

__device__ __forceinline__ uint32_t swz(int r, int q) {
    return (uint32_t)(r * 64 + ((q ^ ((r >> 1) & 3)) << 4));
}

__device__ __forceinline__ void load_chunk(uint32_t sstage, const GP* __restrict__ p,
                                           int kt, int cy, int cx, int tid) {
    const bf16 *Ah, *Al;
    int ka, sA;
    if (kt < p->K1) { Ah = p->Ahi;  Al = p->Alo;  ka = kt;         sA = p->ldA1; }
    else            { Ah = p->A2hi; Al = p->A2lo; ka = kt - p->K1; sA = p->ldA2; }
    const bf16* Bh = p->Bhi;
    const bf16* Bl = p->Blo;
    const int sB = p->ldB;
    #pragma unroll
    for (int i = 0; i < 2; i++) {
        int u = tid + i * 256;       // 0..511
        int r = u >> 2, q = u & 3;
        uint32_t so = swz(r, q);
        size_t ga = (size_t)(cy + r) * sA + ka + q * 8;
        size_t gb = (size_t)(cx + r) * sB + kt + q * 8;
        cp_async16(sstage + T_AHI + so, Ah + ga);
        cp_async16(sstage + T_ALO + so, Al + ga);
        cp_async16(sstage + T_BHI + so, Bh + gb);
        cp_async16(sstage + T_BLO + so, Bl + gb);
    }
}

__global__ __launch_bounds__(256, 2)
void gemm_uni(GP p0, GP p1, int n0) {
    extern __shared__ char smem[];
    const uint32_t sb = smem_u32(smem);
    int id = blockIdx.x;
    const GP* __restrict__ p;
    if (id < n0) p = &p0;
    else { p = &p1; id -= n0; }

    const int tid  = threadIdx.x;
    const int lane = tid & 31;
    const int wid  = tid >> 5;
    const int wm   = wid >> 2;
    const int wn   = wid & 3;
    const int cx   = (id % p->gx) * BN;
    const int cy   = (id / p->gx) * BM;
    const int NCK  = p->Kloop >> 5;

    float acc[4][4][4];
    #pragma unroll
    for (int i = 0; i < 4; i++)
        #pragma unroll
        for (int j = 0; j < 4; j++)
            #pragma unroll
            for (int k = 0; k < 4; k++) acc[i][j][k] = 0.0f;

    const int arow = wm * 64 + (lane & 15);
    const int abit = (lane >> 4) & 1;
    const int asw  = (arow >> 1) & 3;
    const int brow = wn * 32 + (lane & 7) + ((lane & 16) ? 8 : 0);
    const int bbit = (lane >> 3) & 1;
    const int bsw  = (brow >> 1) & 3;
    uint32_t aofk[2], bofk[2];
    #pragma unroll
    for (int ks = 0; ks < 2; ks++) {
        aofk[ks] = (uint32_t)(arow * 64 + ((((ks << 1) | abit) ^ asw) << 4));
        bofk[ks] = (uint32_t)(brow * 64 + ((((ks << 1) | bbit) ^ bsw) << 4));
    }

    // prefetch chunks 0,1
    #pragma unroll
    for (int c = 0; c < STAGES - 1; c++) {
        if (c < NCK)
            load_chunk(sb + c * STAGE_BYTES, p, c * BK, cy, cx, tid);
        cp_commit();
    }

    int bufc = 0;
    for (int c = 0; c < NCK; c++) {
        if (c == NCK - 1) cp_wait<0>(); else cp_wait<1>();
        __syncthreads();
        if (c + 2 < NCK) {
            int nb = bufc + 2; if (nb >= STAGES) nb -= STAGES;
            load_chunk(sb + nb * STAGE_BYTES, p, (c + 2) * BK, cy, cx, tid);
            cp_commit();
        }

        const uint32_t st = sb + bufc * STAGE_BYTES;
        bufc++; if (bufc >= STAGES) bufc = 0;

        #pragma unroll
        for (int ks = 0; ks < 2; ks++) {
            uint32_t a[4][4], b[4][2];
            // acc += Ahi*Blo
            #pragma unroll
            for (int nf2 = 0; nf2 < 2; nf2++) {
                uint32_t r0, r1, r2, r3;
                ldsm_x4(st + T_BLO + bofk[ks] + nf2 * 1024, r0, r1, r2, r3);
                b[nf2 * 2 + 0][0] = r0; b[nf2 * 2 + 0][1] = r1;
                b[nf2 * 2 + 1][0] = r2; b[nf2 * 2 + 1][1] = r3;
            }
            #pragma unroll
            for (int mf = 0; mf < 4; mf++)
                ldsm_x4(st + T_AHI + aofk[ks] + mf * 1024,
                        a[mf][0], a[mf][1], a[mf][2], a[mf][3]);
            #pragma unroll
            for (int mf = 0; mf < 4; mf++)
                #pragma unroll
                for (int nf = 0; nf < 4; nf++)
                    mma_bf16(acc[mf][nf], a[mf], b[nf]);
            // acc += Ahi*Bhi
            #pragma unroll
            for (int nf2 = 0; nf2 < 2; nf2++) {
                uint32_t r0, r1, r2, r3;
                ldsm_x4(st + T_BHI + bofk[ks] + nf2 * 1024, r0, r1, r2, r3);
                b[nf2 * 2 + 0][0] = r0; b[nf2 * 2 + 0][1] = r1;
                b[nf2 * 2 + 1][0] = r2; b[nf2 * 2 + 1][1] = r3;
            }
            #pragma unroll
            for (int mf = 0; mf < 4; mf++)
                #pragma unroll
                for (int nf = 0; nf < 4; nf++)
                    mma_bf16(acc[mf][nf], a[mf], b[nf]);
            // acc += Alo*Bhi
            #pragma unroll
            for (int mf = 0; mf < 4; mf++)
                ldsm_x4(st + T_ALO + aofk[ks] + mf * 1024,
                        a[mf][0], a[mf][1], a[mf][2], a[mf][3]);
            #pragma unroll
            for (int mf = 0; mf < 4; mf++)
                #pragma unroll
                for (int nf = 0; nf < 4; nf++)
                    mma_bf16(acc[mf][nf], a[mf], b[nf]);
        }
        __syncthreads();
    }

    // ---------------- epilogue -----------------------------------------------
    const int gid = lane >> 2;
    const int tig = lane & 3;
    const int ldC = p->ldC;
    const int biasmode = p->biasmode;
    const int relu = p->relu;
    const int split = p->split;
    #pragma unroll
    for (int mf = 0; mf < 4; mf++) {
        const int row0 = cy + wm * 64 + mf * 16 + gid;
        float rb0 = 0.f, rb1 = 0.f;
        if (biasmode == 2) { rb0 = p->bias[row0]; rb1 = p->bias[row0 + 8]; }
        #pragma unroll
        for (int nf = 0; nf < 4; nf++) {
            const int col = cx + wn * 32 + nf * 8 + tig * 2;
            float v0 = acc[mf][nf][0], v1 = acc[mf][nf][1];
            float v2 = acc[mf][nf][2], v3 = acc[mf][nf][3];
            if (biasmode == 1) {
                float b0 = p->bias[col], b1 = p->bias[col + 1];
                v0 += b0; v1 += b1; v2 += b0; v3 += b1;
            } else if (biasmode == 2) {
                v0 += rb0; v1 += rb0; v2 += rb1; v3 += rb1;
            }
            if (relu) {
                v0 = fmaxf(v0, 0.f); v1 = fmaxf(v1, 0.f);
                v2 = fmaxf(v2, 0.f); v3 = fmaxf(v3, 0.f);
            }
            if (!split) {
                *(float2*)(p->Cf + (size_t)row0 * ldC + col)       = make_float2(v0, v1);
                *(float2*)(p->Cf + (size_t)(row0 + 8) * ldC + col) = make_float2(v2, v3);
            } else {
                bf16 h0 = __float2bfloat16(v0), h1 = __float2bfloat16(v1);
                bf16 h2 = __float2bfloat16(v2), h3 = __float2bfloat16(v3);
                bf16 l0 = __float2bfloat16(v0 - __bfloat162float(h0));
                bf16 l1 = __float2bfloat16(v1 - __bfloat162float(h1));
                bf16 l2 = __float2bfloat16(v2 - __bfloat162float(h2));
                bf16 l3 = __float2bfloat16(v3 - __bfloat162float(h3));
                __nv_bfloat162 hp0; hp0.x = h0; hp0.y = h1;
                __nv_bfloat162 hp1; hp1.x = h2; hp1.y = h3;
                __nv_bfloat162 lp0; lp0.x = l0; lp0.y = l1;
                __nv_bfloat162 lp1; lp1.x = l2; lp1.y = l3;
                *(__nv_bfloat162*)(p->Chi + (size_t)row0 * ldC + col)       = hp0;
                *(__nv_bfloat162*)(p->Chi + (size_t)(row0 + 8) * ldC + col) = hp1;
                *(__nv_bfloat162*)(p->Clo + (size_t)row0 * ldC + col)       = lp0;
                *(__nv_bfloat162*)(p->Clo + (size_t)(row0 + 8) * ldC + col) = lp1;
            }
        }
    }
}

// ---------------- elementwise kernels -----------------------------------------
__global__ void pe_table_kernel(float* invden, float* colsum) {
    int k = blockIdx.x * blockDim.x + threadIdx.x;    // 512 entries
    if (k < DD / 2)
        invden[k] = powf(10000.0f, -(float)(2 * k) / (float)DD);
    if (k < DD) colsum[k] = 0.0f;
}

__device__ __forceinline__ float pe_val_t(const float* __restrict__ invden, int pos, int j) {
    float arg = (float)pos * invden[j >> 1];
    return (j & 1) ? cosf(arg) : sinf(arg);
}

#define CS_ROWS 128
__global__ void colsum_kernel(const float* __restrict__ X,
                              const float* __restrict__ invden,
                              float* __restrict__ colsum) {
    int j  = blockIdx.x * blockDim.x + threadIdx.x;
    int r0 = blockIdx.y * CS_ROWS;
    float inv = invden[j >> 1];
    bool odd = (j & 1);
    float s = 0.0f;
    #pragma unroll 4
    for (int i = 0; i < CS_ROWS; i++) {
        int pos = r0 + i;
        float arg = (float)pos * inv;
        float pe = odd ? cosf(arg) : sinf(arg);
        s += pe * X[(size_t)pos * DD + j];
    }
    atomicAdd(&colsum[j], s);
}

__device__ __forceinline__ void split_store(bf16* hi, bf16* lo, size_t idx, float v) {
    bf16 h = __float2bfloat16(v);
    hi[idx] = h;
    lo[idx] = __float2bfloat16(v - __bfloat162float(h));
}

__global__ void loo_split_kernel(const float* __restrict__ X,
                                 const float* __restrict__ invden,
                                 const float* __restrict__ colsum,
                                 bf16* __restrict__ lhi, bf16* __restrict__ llo,
                                 bf16* __restrict__ xhi, bf16* __restrict__ xlo) {
    int idx = blockIdx.x * blockDim.x + threadIdx.x;   // over N*D
    int row = idx >> 10;
    int j   = idx & 1023;
    float x = X[idx];
    split_store(xhi, xlo, idx, x);
    float e = pe_val_t(invden, row, j) * x;
    float v = (colsum[j] - e) * (1.0f / (float)(NN - 1));
    split_store(lhi, llo, idx, v);
}

// transpose + split: src [R][C] fp32 -> dst [C][R] bf16 hi/lo
__global__ void tsplit_kernel(const float* __restrict__ src,
                              bf16* __restrict__ dhi, bf16* __restrict__ dlo,
                              int R, int C) {
    __shared__ float t[32][33];
    int bx = blockIdx.x * 32;
    int by = blockIdx.y * 32;
    int tx = threadIdx.x, ty = threadIdx.y;
    #pragma unroll
    for (int i = 0; i < 4; i++)
        t[ty + i * 8][tx] = src[(size_t)(by + ty + i * 8) * C + bx + tx];
    __syncthreads();
    #pragma unroll
    for (int i = 0; i < 4; i++) {
        float v = t[tx][ty + i * 8];
        split_store(dhi, dlo, (size_t)(bx + ty + i * 8) * R + by + tx, v);
    }
}

// row softmax over scoresA+scoresB; writes att split bf16
__global__ void softmax_split_kernel(const float* __restrict__ SA,
                                     const float* __restrict__ SB,
                                     bf16* __restrict__ ahi, bf16* __restrict__ alo, int n) {
    __shared__ float red[8];
    __shared__ float buf[4096];
    const float* rowA = SA + (size_t)blockIdx.x * n;
    const float* rowB = SB + (size_t)blockIdx.x * n;
    int tid = threadIdx.x;
    int lane = tid & 31, warp = tid >> 5;

    float m = -1e30f;
    for (int j = tid; j < n; j += 256) {
        float v = rowA[j] + rowB[j];
        buf[j] = v;
        m = fmaxf(m, v);
    }
    #pragma unroll
    for (int o = 16; o > 0; o >>= 1) m = fmaxf(m, __shfl_xor_sync(0xffffffffu, m, o));
    if (lane == 0) red[warp] = m;
    __syncthreads();
    if (tid < 8) {
        float v = red[tid];
        #pragma unroll
        for (int o = 4; o > 0; o >>= 1) v = fmaxf(v, __shfl_xor_sync(0xffu, v, o));
        if (tid == 0) red[0] = v;
    }
    __syncthreads();
    m = red[0];
    __syncthreads();

    float s = 0.0f;
    for (int j = tid; j < n; j += 256) {
        float e = __expf(buf[j] - m);
        buf[j] = e;
        s += e;
    }
    #pragma unroll
    for (int o = 16; o > 0; o >>= 1) s += __shfl_xor_sync(0xffffffffu, s, o);
    if (lane == 0) red[warp] = s;
    __syncthreads();
    if (tid < 8) {
        float v = red[tid];
        #pragma unroll
        for (int o = 4; o > 0; o >>= 1) v += __shfl_xor_sync(0xffu, v, o);
        if (tid == 0) red[0] = v;
    }
    __syncthreads();
    float inv = 1.0f / red[0];
    size_t base = (size_t)blockIdx.x * n;
    for (int j = tid; j < n; j += 256) {
        float a = buf[j] * inv;
        split_store(ahi, alo, base + j, a);
    }
}

// ---------------- driver ------------------------------------------------------
extern "C" void kernel_launch(void* const* d_in, const int* in_sizes, int n_in,
                              void* d_out, int out_size) {
    const float* X  = (const float*)d_in[0];
    const float* Wv = (const float*)d_in[2];
    const float* bv = (const float*)d_in[3];
    const float* W1 = (const float*)d_in[4];
    const float* b1 = (const float*)d_in[5];
    const float* W2 = (const float*)d_in[6];
    const float* b2 = (const float*)d_in[7];
    float* out = (float*)d_out;

    void* p;
    cudaGetSymbolAddress(&p, g_invden);  float* invden  = (float*)p;
    cudaGetSymbolAddress(&p, g_colsum);  float* colsum  = (float*)p;
    cudaGetSymbolAddress(&p, g_scoresA); float* scoresA = (float*)p;
    cudaGetSymbolAddress(&p, g_scoresB); float* scoresB = (float*)p;
    cudaGetSymbolAddress(&p, g_Xhi);    bf16* Xhi   = (bf16*)p;
    cudaGetSymbolAddress(&p, g_Xlo);    bf16* Xlo   = (bf16*)p;
    cudaGetSymbolAddress(&p, g_loohi);  bf16* loohi = (bf16*)p;
    cudaGetSymbolAddress(&p, g_loolo);  bf16* loolo = (bf16*)p;
    cudaGetSymbolAddress(&p, g_WvThi);  bf16* WvThi = (bf16*)p;
    cudaGetSymbolAddress(&p, g_WvTlo);  bf16* WvTlo = (bf16*)p;
    cudaGetSymbolAddress(&p, g_W1Thi);  bf16* W1Thi = (bf16*)p;
    cudaGetSymbolAddress(&p, g_W1Tlo);  bf16* W1Tlo = (bf16*)p;
    cudaGetSymbolAddress(&p, g_hidhi);  bf16* hdhi  = (bf16*)p;
    cudaGetSymbolAddress(&p, g_hidlo);  bf16* hdlo  = (bf16*)p;
    cudaGetSymbolAddress(&p, g_W2Thi);  bf16* W2Thi = (bf16*)p;
    cudaGetSymbolAddress(&p, g_W2Tlo);  bf16* W2Tlo = (bf16*)p;
    cudaGetSymbolAddress(&p, g_atthi);  bf16* athi  = (bf16*)p;
    cudaGetSymbolAddress(&p, g_attlo);  bf16* atlo  = (bf16*)p;
    cudaGetSymbolAddress(&p, g_VThi);   bf16* VThi  = (bf16*)p;
    cudaGetSymbolAddress(&p, g_VTlo);   bf16* VTlo  = (bf16*)p;

    cudaFuncSetAttribute(gemm_uni, cudaFuncAttributeMaxDynamicSharedMemorySize, GSMEM);

    // --- operand prep --------------------------------------------------------
    pe_table_kernel<<<4, 256>>>(invden, colsum);
    colsum_kernel<<<dim3(DD / 256, NN / CS_ROWS), 256>>>(X, invden, colsum);
    loo_split_kernel<<<(NN * DD) / 256, 256>>>(X, invden, colsum, loohi, loolo, Xhi, Xlo);
    tsplit_kernel<<<dim3(DD / 32, DD / 32),     dim3(32, 8)>>>(Wv, WvThi, WvTlo, DD, DD);
    tsplit_kernel<<<dim3(HH / 32, (2*DD) / 32), dim3(32, 8)>>>(W1, W1Thi, W1Tlo, 2 * DD, HH);
    tsplit_kernel<<<dim3(NN / 32, HH / 32),     dim3(32, 8)>>>(W2, W2Thi, W2Tlo, HH, NN);

    // --- merged GEMM1+GEMM2 ---------------------------------------------------
    // G1: VT = WvT @ X^T + bv(row)  M=1024 N=4096 K=1024, split out, ldC=NN
    GP g1;
    g1.Ahi = WvThi; g1.Alo = WvTlo; g1.A2hi = WvThi; g1.A2lo = WvTlo;
    g1.Bhi = Xhi;   g1.Blo = Xlo;
    g1.bias = bv;   g1.Cf = nullptr; g1.Chi = VThi; g1.Clo = VTlo;
    g1.gx = NN / BN;
    g1.ldA1 = DD; g1.ldA2 = DD; g1.ldB = DD; g1.ldC = NN;
    g1.Kloop = DD; g1.K1 = DD;
    g1.biasmode = 2; g1.relu = 0; g1.split = 1;
    // G2: hidden = relu([X|loo] @ W1T^T + b1)  M=4096 N=2048 K=2048 (K1=1024)
    GP g2;
    g2.Ahi = Xhi; g2.Alo = Xlo; g2.A2hi = loohi; g2.A2lo = loolo;
    g2.Bhi = W1Thi; g2.Blo = W1Tlo;
    g2.bias = b1; g2.Cf = nullptr; g2.Chi = hdhi; g2.Clo = hdlo;
    g2.gx = HH / BN;
    g2.ldA1 = DD; g2.ldA2 = DD; g2.ldB = 2 * DD; g2.ldC = HH;
    g2.Kloop = 2 * DD; g2.K1 = DD;
    g2.biasmode = 1; g2.relu = 1; g2.split = 1;
    {
        int n1 = g1.gx * (DD / BM);          // 256
        int n2 = g2.gx * (NN / BM);          // 512
        gemm_uni<<<n1 + n2, 256, GSMEM>>>(g1, g2, n1);
    }

    // --- split-K GEMM3: scores = hidden @ W2 + b2 -----------------------------
    GP g3a;
    g3a.Ahi = hdhi; g3a.Alo = hdlo; g3a.A2hi = hdhi; g3a.A2lo = hdlo;
    g3a.Bhi = W2Thi; g3a.Blo = W2Tlo;
    g3a.bias = b2; g3a.Cf = scoresA; g3a.Chi = nullptr; g3a.Clo = nullptr;
    g3a.gx = NN / BN;
    g3a.ldA1 = HH; g3a.ldA2 = HH; g3a.ldB = HH; g3a.ldC = NN;
    g3a.Kloop = HH / 2; g3a.K1 = HH / 2;
    g3a.biasmode = 1; g3a.relu = 0; g3a.split = 0;
    GP g3b = g3a;
    g3b.Ahi = hdhi + HH / 2;  g3b.Alo = hdlo + HH / 2;
    g3b.A2hi = g3b.Ahi;       g3b.A2lo = g3b.Alo;
    g3b.Bhi = W2Thi + HH / 2; g3b.Blo = W2Tlo + HH / 2;
    g3b.Cf = scoresB;
    g3b.biasmode = 0;
    {
        int n3 = (NN / BN) * (NN / BM);      // 1024 each
        gemm_uni<<<2 * n3, 256, GSMEM>>>(g3a, g3b, n3);
    }

    // --- softmax -> att split -------------------------------------------------
    softmax_split_kernel<<<NN, 256>>>(scoresA, scoresB, athi, atlo, NN);

    // --- GEMM4: out = att @ V  M=4096 N=1024 K=4096 ---------------------------
    GP g4;
    g4.Ahi = athi; g4.Alo = atlo; g4.A2hi = athi; g4.A2lo = atlo;
    g4.Bhi = VThi; g4.Blo = VTlo;
    g4.bias = nullptr; g4.Cf = out; g4.Chi = nullptr; g4.Clo = nullptr;
    g4.gx = DD / BN;
    g4.ldA1 = NN; g4.ldA2 = NN; g4.ldB = NN; g4.ldC = DD;
    g4.Kloop = NN; g4.K1 = NN;
    g4.biasmode = 0; g4.relu = 0; g4.split = 0;
    {
        int n4 = g4.gx * (NN / BM);          // 256
        gemm_uni<<<n4, 256, GSMEM>>>(g4, g4, n4);
    }
}